// round 1
// baseline (speedup 1.0000x reference)
#include <cuda_runtime.h>
#include <math.h>

#define BM   128   // query rows per CTA (= threads)
#define BN   32    // keys per SMEM tile
#define HEADS 16
#define HKV   4
#define GQA   4    // HEADS / HKV
#define DH    64

__global__ __launch_bounds__(BM) void varlen_attn_kernel(
    const float* __restrict__ q,
    const float* __restrict__ kv,
    const int*   __restrict__ cu,
    float*       __restrict__ out)
{
    const int seq   = blockIdx.y;
    const int h     = blockIdx.z;
    const int start = cu[seq];
    const int L     = cu[seq + 1] - start;
    const int m0    = blockIdx.x * BM;
    if (m0 >= L) return;

    const int  hkv    = h / GQA;
    const int  tid    = threadIdx.x;
    const int  qpos   = m0 + tid;          // query position within sequence
    const bool active = qpos < L;

    __shared__ float4 Ks[BN * (DH / 4)];   // 8 KB
    __shared__ float4 Vs[BN * (DH / 4)];   // 8 KB

    // softmax scale folded with log2(e) so we can use exp2f (MUFU.EX2)
    const float SCALE = 0.125f * 1.4426950408889634f;

    float qr[DH];
    if (active) {
        const float4* qp = reinterpret_cast<const float4*>(
            q + ((size_t)(start + qpos) * HEADS + h) * DH);
        #pragma unroll
        for (int c = 0; c < DH / 4; c++) {
            float4 v = qp[c];
            qr[4*c+0] = v.x * SCALE;
            qr[4*c+1] = v.y * SCALE;
            qr[4*c+2] = v.z * SCALE;
            qr[4*c+3] = v.w * SCALE;
        }
    }

    float acc[DH];
    #pragma unroll
    for (int d = 0; d < DH; d++) acc[d] = 0.f;
    float mrow = -INFINITY;
    float lrow = 0.f;

    const int klim_cta = (L < m0 + BM) ? L : (m0 + BM);   // keys needed by this CTA
    const int ntiles   = (klim_cta + BN - 1) / BN;
    const int klim_row = active ? ((qpos + 1 < L) ? qpos + 1 : L) : 0;

    for (int t = 0; t < ntiles; t++) {
        const int k0 = t * BN;
        __syncthreads();
        // cooperative K/V tile load, zero-padded past L
        #pragma unroll
        for (int i = tid; i < BN * (DH / 4); i += BM) {
            int row = i >> 4;         // DH/4 == 16
            int c4  = i & 15;
            int kp  = k0 + row;
            float4 kk = make_float4(0.f, 0.f, 0.f, 0.f);
            float4 vv = make_float4(0.f, 0.f, 0.f, 0.f);
            if (kp < L) {
                const float* kb = kv + (size_t)(start + kp) * (2 * HKV * DH) + hkv * DH;
                kk = *reinterpret_cast<const float4*>(kb + 4 * c4);
                vv = *reinterpret_cast<const float4*>(kb + HKV * DH + 4 * c4);
            }
            Ks[i] = kk;
            Vs[i] = vv;
        }
        __syncthreads();

        if (active && qpos >= k0) {
            float s[BN];
            float tmax = -INFINITY;
            #pragma unroll
            for (int j = 0; j < BN; j++) {
                float d0 = 0.f, d1 = 0.f, d2 = 0.f, d3 = 0.f;
                #pragma unroll
                for (int c = 0; c < DH / 4; c++) {
                    float4 kk = Ks[j * (DH / 4) + c];   // broadcast LDS.128
                    d0 = fmaf(qr[4*c+0], kk.x, d0);
                    d1 = fmaf(qr[4*c+1], kk.y, d1);
                    d2 = fmaf(qr[4*c+2], kk.z, d2);
                    d3 = fmaf(qr[4*c+3], kk.w, d3);
                }
                float dot = (d0 + d1) + (d2 + d3);
                s[j] = (k0 + j < klim_row) ? dot : -1e30f;
                tmax = fmaxf(tmax, s[j]);
            }
            float mnew = fmaxf(mrow, tmax);
            float corr = exp2f(mrow - mnew);     // 0 on first tile (mrow = -inf)
            lrow *= corr;
            #pragma unroll
            for (int d = 0; d < DH; d++) acc[d] *= corr;
            #pragma unroll
            for (int j = 0; j < BN; j++) {
                float p = exp2f(s[j] - mnew);    // masked lanes -> exactly 0
                lrow += p;
                #pragma unroll
                for (int c = 0; c < DH / 4; c++) {
                    float4 vv = Vs[j * (DH / 4) + c];
                    acc[4*c+0] = fmaf(p, vv.x, acc[4*c+0]);
                    acc[4*c+1] = fmaf(p, vv.y, acc[4*c+1]);
                    acc[4*c+2] = fmaf(p, vv.z, acc[4*c+2]);
                    acc[4*c+3] = fmaf(p, vv.w, acc[4*c+3]);
                }
            }
            mrow = mnew;
        }
    }

    if (active) {
        float inv = 1.f / lrow;
        float4* op = reinterpret_cast<float4*>(
            out + ((size_t)(start + qpos) * HEADS + h) * DH);
        #pragma unroll
        for (int c = 0; c < DH / 4; c++) {
            op[c] = make_float4(acc[4*c+0] * inv, acc[4*c+1] * inv,
                                acc[4*c+2] * inv, acc[4*c+3] * inv);
        }
    }
}

extern "C" void kernel_launch(void* const* d_in, const int* in_sizes, int n_in,
                              void* d_out, int out_size)
{
    const float* q  = (const float*)d_in[0];
    const float* kv = (const float*)d_in[1];
    const int*   cu = (const int*)d_in[2];
    // lengths live on device; size grid from element counts (upper bound per seq)
    const int total   = in_sizes[0] / (HEADS * DH);
    const int nseq    = in_sizes[2] - 1;
    const int mblocks = (total + BM - 1) / BM;

    dim3 grid(mblocks, nseq, HEADS);
    varlen_attn_kernel<<<grid, BM>>>(q, kv, cu, (float*)d_out);
}

// round 3
// speedup vs baseline: 4.8781x; 4.8781x over previous
#include <cuda_runtime.h>
#include <cuda_bf16.h>
#include <cstdint>

#define HEADS 16
#define HKV   4
#define DH    64
#define BM    128
#define BN    64
#define NTH   256

#define SW128(x) ((x) ^ (((x) >> 3) & 0x70))

// smem: K hi/lo, V hi/lo (64 rows x 128B each). Q staging reuses [0,32KB).
#define KH_OFF 0
#define KL_OFF 8192
#define VH_OFF 16384
#define VL_OFF 24576

__device__ __forceinline__ uint32_t smem_u32(const void* p) {
    uint32_t a;
    asm("{ .reg .u64 t; cvta.to.shared.u64 t, %1; cvt.u32.u64 %0, t; }"
        : "=r"(a) : "l"(p));
    return a;
}

__device__ __forceinline__ float ex2(float x) {
    float y; asm("ex2.approx.f32 %0, %1;" : "=f"(y) : "f"(x)); return y;
}

__device__ __forceinline__ void ldsm_x4(uint32_t* r, uint32_t addr) {
    asm volatile("ldmatrix.sync.aligned.m8n8.x4.shared.b16 {%0,%1,%2,%3}, [%4];"
        : "=r"(r[0]), "=r"(r[1]), "=r"(r[2]), "=r"(r[3]) : "r"(addr));
}
__device__ __forceinline__ void ldsm_x4t(uint32_t* r, uint32_t addr) {
    asm volatile("ldmatrix.sync.aligned.m8n8.x4.trans.shared.b16 {%0,%1,%2,%3}, [%4];"
        : "=r"(r[0]), "=r"(r[1]), "=r"(r[2]), "=r"(r[3]) : "r"(addr));
}

__device__ __forceinline__ void mma16816(float* d, const uint32_t* a, const uint32_t* b) {
    asm volatile("mma.sync.aligned.m16n8k16.row.col.f32.bf16.bf16.f32 "
        "{%0,%1,%2,%3}, {%4,%5,%6,%7}, {%8,%9}, {%0,%1,%2,%3};"
        : "+f"(d[0]), "+f"(d[1]), "+f"(d[2]), "+f"(d[3])
        : "r"(a[0]), "r"(a[1]), "r"(a[2]), "r"(a[3]), "r"(b[0]), "r"(b[1]));
}

// split x into bf16 hi + bf16 lo(residual); pack pairs little-endian (x0 low)
__device__ __forceinline__ void splitp(float x0, float x1, uint32_t& hi, uint32_t& lo) {
    __nv_bfloat16 h0 = __float2bfloat16(x0);
    __nv_bfloat16 h1 = __float2bfloat16(x1);
    hi = ((uint32_t)__bfloat16_as_ushort(h1) << 16) | (uint32_t)__bfloat16_as_ushort(h0);
    float r0 = x0 - __bfloat162float(h0);
    float r1 = x1 - __bfloat162float(h1);
    asm("cvt.rn.bf16x2.f32 %0, %1, %2;" : "=r"(lo) : "f"(r1), "f"(r0));
}

__global__ __launch_bounds__(NTH, 2) void varlen_attn_hmma(
    const float* __restrict__ q,
    const float* __restrict__ kv,
    const int*   __restrict__ cu,
    float*       __restrict__ out)
{
    const int seq   = blockIdx.y;
    const int h     = blockIdx.z;
    const int start = cu[seq];
    const int L     = cu[seq + 1] - start;
    const int m0    = blockIdx.x * BM;
    if (m0 >= L) return;

    __shared__ __align__(1024) uint8_t sm[32768];
    const uint32_t smb = smem_u32(sm);

    const int tid  = threadIdx.x;
    const int wid  = tid >> 5;
    const int lane = tid & 31;
    const int hkv  = h >> 2;
    const float SCALE = 0.125f * 1.4426950408889634f;

    // ---- stage Q (scaled, split bf16 hi/lo) into smem, then ldmatrix to regs ----
    #pragma unroll
    for (int it = 0; it < 16; it++) {
        int u = it * NTH + tid;
        int row = u >> 5, c2 = u & 31;
        float2 qv = make_float2(0.f, 0.f);
        if (m0 + row < L)
            qv = *reinterpret_cast<const float2*>(
                q + ((size_t)(start + m0 + row) * HEADS + h) * DH + 2 * c2);
        qv.x *= SCALE; qv.y *= SCALE;
        uint32_t hi, lo;
        splitp(qv.x, qv.y, hi, lo);
        uint32_t sw = SW128((uint32_t)(row * 128 + c2 * 4));
        *reinterpret_cast<uint32_t*>(sm + sw)          = hi;
        *reinterpret_cast<uint32_t*>(sm + 16384 + sw)  = lo;
    }
    __syncthreads();

    uint32_t qh[4][4], ql[4][4];
    {
        int qrow = wid * 16 + (lane & 15);
        #pragma unroll
        for (int kk = 0; kk < 4; kk++) {
            uint32_t off = SW128((uint32_t)(qrow * 128 + kk * 32 + ((lane >> 4) & 1) * 16));
            ldsm_x4(qh[kk], smb + off);
            ldsm_x4(ql[kk], smb + 16384 + off);
        }
    }

    // ---- per-thread state ----
    float O[8][4];
    #pragma unroll
    for (int j = 0; j < 8; j++)
        #pragma unroll
        for (int e = 0; e < 4; e++) O[j][e] = 0.f;
    float mrow0 = -1e30f, mrow1 = -1e30f, lrow0 = 0.f, lrow1 = 0.f;

    const int qpos0 = m0 + wid * 16 + (lane >> 2);
    const int qpos1 = qpos0 + 8;
    const int klim0 = (qpos0 + 1 < L) ? qpos0 + 1 : L;
    const int klim1 = (qpos1 + 1 < L) ? qpos1 + 1 : L;
    const int qmax_warp = m0 + wid * 16 + 15;
    const int qmin_warp = m0 + wid * 16;

    const int klim_cta = (L < m0 + BM) ? L : (m0 + BM);
    const int ntiles   = (klim_cta + BN - 1) / BN;

    for (int t = 0; t < ntiles; t++) {
        const int k0 = t * BN;
        __syncthreads();

        // ---- cooperative K/V tile load + split ----
        #pragma unroll
        for (int it = 0; it < 8; it++) {
            int u = it * NTH + tid;
            int key = u >> 5, c2 = u & 31;
            int kp = k0 + key;
            float2 k2 = make_float2(0.f, 0.f), v2 = make_float2(0.f, 0.f);
            if (kp < L) {
                const float* b = kv + (size_t)(start + kp) * (2 * HKV * DH) + hkv * DH + 2 * c2;
                k2 = *reinterpret_cast<const float2*>(b);
                v2 = *reinterpret_cast<const float2*>(b + HKV * DH);
            }
            uint32_t sw = SW128((uint32_t)(key * 128 + c2 * 4));
            uint32_t hi, lo;
            splitp(k2.x, k2.y, hi, lo);
            *reinterpret_cast<uint32_t*>(sm + KH_OFF + sw) = hi;
            *reinterpret_cast<uint32_t*>(sm + KL_OFF + sw) = lo;
            splitp(v2.x, v2.y, hi, lo);
            *reinterpret_cast<uint32_t*>(sm + VH_OFF + sw) = hi;
            *reinterpret_cast<uint32_t*>(sm + VL_OFF + sw) = lo;
        }
        __syncthreads();

        if (k0 > qmax_warp) continue;   // fully-masked tile for this warp

        // ---- S = Q K^T (split bf16, 3 MMAs) ----
        float S[8][4];
        #pragma unroll
        for (int j = 0; j < 8; j++)
            #pragma unroll
            for (int e = 0; e < 4; e++) S[j][e] = 0.f;

        {
            int key = ((lane >> 4) & 1) * 8 + (lane & 7);
            int dhalf = ((lane >> 3) & 1) * 16;
            #pragma unroll
            for (int jp = 0; jp < 4; jp++) {
                #pragma unroll
                for (int kk = 0; kk < 4; kk++) {
                    uint32_t off = SW128((uint32_t)((16 * jp + key) * 128 + kk * 32 + dhalf));
                    uint32_t bh[4], bl[4];
                    ldsm_x4(bh, smb + KH_OFF + off);
                    ldsm_x4(bl, smb + KL_OFF + off);
                    mma16816(S[2*jp],   qh[kk], bh);
                    mma16816(S[2*jp],   qh[kk], bl);
                    mma16816(S[2*jp],   ql[kk], bh);
                    mma16816(S[2*jp+1], qh[kk], bh + 2);
                    mma16816(S[2*jp+1], qh[kk], bl + 2);
                    mma16816(S[2*jp+1], ql[kk], bh + 2);
                }
            }
        }

        // ---- causal mask + online softmax ----
        const bool full = (k0 + BN <= L) && (k0 + BN <= qmin_warp + 1);
        float tmax0 = -1e30f, tmax1 = -1e30f;
        if (full) {
            #pragma unroll
            for (int j = 0; j < 8; j++) {
                tmax0 = fmaxf(tmax0, fmaxf(S[j][0], S[j][1]));
                tmax1 = fmaxf(tmax1, fmaxf(S[j][2], S[j][3]));
            }
        } else {
            const int jm0 = klim0 - k0, jm1 = klim1 - k0;
            #pragma unroll
            for (int j = 0; j < 8; j++) {
                int kg = 8 * j + 2 * (lane & 3);
                S[j][0] = (kg     < jm0) ? S[j][0] : -1e30f;
                S[j][1] = (kg + 1 < jm0) ? S[j][1] : -1e30f;
                S[j][2] = (kg     < jm1) ? S[j][2] : -1e30f;
                S[j][3] = (kg + 1 < jm1) ? S[j][3] : -1e30f;
                tmax0 = fmaxf(tmax0, fmaxf(S[j][0], S[j][1]));
                tmax1 = fmaxf(tmax1, fmaxf(S[j][2], S[j][3]));
            }
        }
        tmax0 = fmaxf(tmax0, __shfl_xor_sync(0xffffffffu, tmax0, 1));
        tmax0 = fmaxf(tmax0, __shfl_xor_sync(0xffffffffu, tmax0, 2));
        tmax1 = fmaxf(tmax1, __shfl_xor_sync(0xffffffffu, tmax1, 1));
        tmax1 = fmaxf(tmax1, __shfl_xor_sync(0xffffffffu, tmax1, 2));

        float mnew0 = fmaxf(mrow0, tmax0);
        float mnew1 = fmaxf(mrow1, tmax1);
        float corr0 = ex2(mrow0 - mnew0);
        float corr1 = ex2(mrow1 - mnew1);
        mrow0 = mnew0; mrow1 = mnew1;
        lrow0 *= corr0; lrow1 *= corr1;
        #pragma unroll
        for (int j = 0; j < 8; j++) {
            O[j][0] *= corr0; O[j][1] *= corr0;
            O[j][2] *= corr1; O[j][3] *= corr1;
        }
        float ls0 = 0.f, ls1 = 0.f;
        #pragma unroll
        for (int j = 0; j < 8; j++) {
            S[j][0] = ex2(S[j][0] - mnew0);
            S[j][1] = ex2(S[j][1] - mnew0);
            S[j][2] = ex2(S[j][2] - mnew1);
            S[j][3] = ex2(S[j][3] - mnew1);
            ls0 += S[j][0] + S[j][1];
            ls1 += S[j][2] + S[j][3];
        }
        lrow0 += ls0; lrow1 += ls1;

        // ---- O += P V (split bf16, 3 MMAs), P frags built from S in-place ----
        {
            int vkey = (lane & 15);
            int dhalf = ((lane >> 4) & 1) * 16;
            #pragma unroll
            for (int kk = 0; kk < 4; kk++) {
                uint32_t ph[4], pl[4];
                splitp(S[2*kk][0],   S[2*kk][1],   ph[0], pl[0]);
                splitp(S[2*kk][2],   S[2*kk][3],   ph[1], pl[1]);
                splitp(S[2*kk+1][0], S[2*kk+1][1], ph[2], pl[2]);
                splitp(S[2*kk+1][2], S[2*kk+1][3], ph[3], pl[3]);
                #pragma unroll
                for (int jp = 0; jp < 4; jp++) {
                    uint32_t off = SW128((uint32_t)((16 * kk + vkey) * 128 + jp * 32 + dhalf));
                    uint32_t bh[4], bl[4];
                    ldsm_x4t(bh, smb + VH_OFF + off);
                    ldsm_x4t(bl, smb + VL_OFF + off);
                    mma16816(O[2*jp],   ph, bh);
                    mma16816(O[2*jp],   ph, bl);
                    mma16816(O[2*jp],   pl, bh);
                    mma16816(O[2*jp+1], ph, bh + 2);
                    mma16816(O[2*jp+1], ph, bl + 2);
                    mma16816(O[2*jp+1], pl, bh + 2);
                }
            }
        }
    }

    // ---- epilogue: reduce l across quad, normalize, store ----
    lrow0 += __shfl_xor_sync(0xffffffffu, lrow0, 1);
    lrow0 += __shfl_xor_sync(0xffffffffu, lrow0, 2);
    lrow1 += __shfl_xor_sync(0xffffffffu, lrow1, 1);
    lrow1 += __shfl_xor_sync(0xffffffffu, lrow1, 2);
    float inv0 = 1.f / lrow0;
    float inv1 = 1.f / lrow1;

    const int col = 2 * (lane & 3);
    if (qpos0 < L) {
        float* o0 = out + ((size_t)(start + qpos0) * HEADS + h) * DH;
        #pragma unroll
        for (int jd = 0; jd < 8; jd++)
            *reinterpret_cast<float2*>(o0 + 8 * jd + col) =
                make_float2(O[jd][0] * inv0, O[jd][1] * inv0);
    }
    if (qpos1 < L) {
        float* o1 = out + ((size_t)(start + qpos1) * HEADS + h) * DH;
        #pragma unroll
        for (int jd = 0; jd < 8; jd++)
            *reinterpret_cast<float2*>(o1 + 8 * jd + col) =
                make_float2(O[jd][2] * inv1, O[jd][3] * inv1);
    }
}

extern "C" void kernel_launch(void* const* d_in, const int* in_sizes, int n_in,
                              void* d_out, int out_size)
{
    const float* q  = (const float*)d_in[0];
    const float* kv = (const float*)d_in[1];
    const int*   cu = (const int*)d_in[2];
    const int total   = in_sizes[0] / (HEADS * DH);
    const int nseq    = in_sizes[2] - 1;
    const int mblocks = (total + BM - 1) / BM;

    dim3 grid(mblocks, nseq, HEADS);
    varlen_attn_hmma<<<grid, NTH>>>(q, kv, cu, (float*)d_out);
}

// round 4
// speedup vs baseline: 5.5978x; 1.1475x over previous
#include <cuda_runtime.h>
#include <cuda_bf16.h>
#include <cstdint>

#define HEADS 16
#define HKV   4
#define DH    64
#define BM    128
#define BN    64
#define NTH   256
#define TMAX  8192

#define SW128(x) ((x) ^ (((x) >> 3) & 0x70))

// planar bf16 split KV scratch: plane (0=Khi,1=Klo,2=Vhi,3=Vlo)[hkv][token][dim]
__device__ __align__(16) __nv_bfloat16 g_kvsplit[4][HKV][TMAX][DH];

__device__ __forceinline__ uint32_t smem_u32(const void* p) {
    uint32_t a;
    asm("{ .reg .u64 t; cvta.to.shared.u64 t, %1; cvt.u32.u64 %0, t; }"
        : "=r"(a) : "l"(p));
    return a;
}

__device__ __forceinline__ float ex2(float x) {
    float y; asm("ex2.approx.f32 %0, %1;" : "=f"(y) : "f"(x)); return y;
}

__device__ __forceinline__ void ldsm_x4(uint32_t* r, uint32_t addr) {
    asm volatile("ldmatrix.sync.aligned.m8n8.x4.shared.b16 {%0,%1,%2,%3}, [%4];"
        : "=r"(r[0]), "=r"(r[1]), "=r"(r[2]), "=r"(r[3]) : "r"(addr));
}
__device__ __forceinline__ void ldsm_x4t(uint32_t* r, uint32_t addr) {
    asm volatile("ldmatrix.sync.aligned.m8n8.x4.trans.shared.b16 {%0,%1,%2,%3}, [%4];"
        : "=r"(r[0]), "=r"(r[1]), "=r"(r[2]), "=r"(r[3]) : "r"(addr));
}

__device__ __forceinline__ void mma16816(float* d, const uint32_t* a, const uint32_t* b) {
    asm volatile("mma.sync.aligned.m16n8k16.row.col.f32.bf16.bf16.f32 "
        "{%0,%1,%2,%3}, {%4,%5,%6,%7}, {%8,%9}, {%0,%1,%2,%3};"
        : "+f"(d[0]), "+f"(d[1]), "+f"(d[2]), "+f"(d[3])
        : "r"(a[0]), "r"(a[1]), "r"(a[2]), "r"(a[3]), "r"(b[0]), "r"(b[1]));
}

// split x into bf16 hi + bf16 lo(residual); pack pairs little-endian (x0 low)
__device__ __forceinline__ void splitp(float x0, float x1, uint32_t& hi, uint32_t& lo) {
    __nv_bfloat16 h0 = __float2bfloat16(x0);
    __nv_bfloat16 h1 = __float2bfloat16(x1);
    hi = ((uint32_t)__bfloat16_as_ushort(h1) << 16) | (uint32_t)__bfloat16_as_ushort(h0);
    float r0 = x0 - __bfloat162float(h0);
    float r1 = x1 - __bfloat162float(h1);
    asm("cvt.rn.bf16x2.f32 %0, %1, %2;" : "=r"(lo) : "f"(r1), "f"(r0));
}

// ---------------- pre-pass: fp32 KV -> bf16 hi/lo planes ----------------
__global__ void convert_kv_kernel(const float* __restrict__ kv, int nitems) {
    int idx = blockIdx.x * blockDim.x + threadIdx.x;
    if (idx >= nitems) return;               // nitems = total*HKV*32
    int c2  = idx & 31;
    int hk  = (idx >> 5) & 3;
    int tok = idx >> 7;
    const float* base = kv + (size_t)tok * (2 * HKV * DH) + hk * DH + 2 * c2;
    float2 kk = *reinterpret_cast<const float2*>(base);
    float2 vv = *reinterpret_cast<const float2*>(base + HKV * DH);
    uint32_t hi, lo;
    splitp(kk.x, kk.y, hi, lo);
    *reinterpret_cast<uint32_t*>(&g_kvsplit[0][hk][tok][2 * c2]) = hi;
    *reinterpret_cast<uint32_t*>(&g_kvsplit[1][hk][tok][2 * c2]) = lo;
    splitp(vv.x, vv.y, hi, lo);
    *reinterpret_cast<uint32_t*>(&g_kvsplit[2][hk][tok][2 * c2]) = hi;
    *reinterpret_cast<uint32_t*>(&g_kvsplit[3][hk][tok][2 * c2]) = lo;
}

// cp.async one KV tile (all 4 planes) into smem buffer buf with SW128 swizzle
__device__ __forceinline__ void prefetch_tile(uint32_t smb, int buf, int tid,
                                              int hkv, int tok0, int L, int k0) {
    uint32_t dstb = smb + (uint32_t)buf * 32768u;
    #pragma unroll
    for (int p = 0; p < 4; p++) {
        const __nv_bfloat16* plane = &g_kvsplit[p][hkv][0][0];
        #pragma unroll
        for (int i = 0; i < 2; i++) {
            int u   = i * NTH + tid;            // 512 granules of 16B per plane
            int key = u >> 3, g = u & 7;
            uint32_t dst = dstb + (uint32_t)p * 8192u
                         + SW128((uint32_t)(key * 128 + g * 16));
            const void* src = plane + (size_t)(tok0 + key) * DH + g * 8;
            unsigned n = (k0 + key < L) ? 16u : 0u;   // zfill OOB keys
            asm volatile("cp.async.cg.shared.global [%0], [%1], 16, %2;"
                         :: "r"(dst), "l"(src), "r"(n));
        }
    }
}

__global__ __launch_bounds__(NTH, 2) void varlen_attn_hmma2(
    const float* __restrict__ q,
    const int*   __restrict__ cu,
    float*       __restrict__ out)
{
    const int seq   = blockIdx.y;
    const int h     = blockIdx.z;
    const int start = cu[seq];
    const int L     = cu[seq + 1] - start;
    const int m0    = (gridDim.x - 1 - blockIdx.x) * BM;   // longest CTAs first
    if (m0 >= L) return;

    extern __shared__ uint8_t sm[];
    const uint32_t smb = smem_u32(sm);

    const int tid  = threadIdx.x;
    const int wid  = tid >> 5;
    const int lane = tid & 31;
    const int hkv  = h >> 2;
    const float SCALE = 0.125f * 1.4426950408889634f;

    const int klim_cta = (L < m0 + BM) ? L : (m0 + BM);
    const int ntiles   = (klim_cta + BN - 1) / BN;

    // kick off tile 0 load immediately (overlaps Q conversion)
    prefetch_tile(smb, 0, tid, hkv, start, L, 0);
    asm volatile("cp.async.commit_group;" ::: "memory");

    // ---- stage Q (scaled, split bf16 hi/lo) into buf1 region ----
    #pragma unroll
    for (int it = 0; it < 16; it++) {
        int u = it * NTH + tid;
        int row = u >> 5, c2 = u & 31;
        float2 qv = make_float2(0.f, 0.f);
        if (m0 + row < L)
            qv = *reinterpret_cast<const float2*>(
                q + ((size_t)(start + m0 + row) * HEADS + h) * DH + 2 * c2);
        qv.x *= SCALE; qv.y *= SCALE;
        uint32_t hi, lo;
        splitp(qv.x, qv.y, hi, lo);
        uint32_t sw = SW128((uint32_t)(row * 128 + c2 * 4));
        *reinterpret_cast<uint32_t*>(sm + 32768 + sw) = hi;
        *reinterpret_cast<uint32_t*>(sm + 49152 + sw) = lo;
    }
    __syncthreads();

    uint32_t qh[4][4], ql[4][4];
    {
        int qrow = wid * 16 + (lane & 15);
        #pragma unroll
        for (int kk = 0; kk < 4; kk++) {
            uint32_t off = SW128((uint32_t)(qrow * 128 + kk * 32 + ((lane >> 4) & 1) * 16));
            ldsm_x4(qh[kk], smb + 32768 + off);
            ldsm_x4(ql[kk], smb + 49152 + off);
        }
    }

    // ---- per-thread state ----
    float O[8][4];
    #pragma unroll
    for (int j = 0; j < 8; j++)
        #pragma unroll
        for (int e = 0; e < 4; e++) O[j][e] = 0.f;
    float mrow0 = -1e30f, mrow1 = -1e30f, lrow0 = 0.f, lrow1 = 0.f;

    const int qpos0 = m0 + wid * 16 + (lane >> 2);
    const int qpos1 = qpos0 + 8;
    const int klim0 = (qpos0 + 1 < L) ? qpos0 + 1 : L;
    const int klim1 = (qpos1 + 1 < L) ? qpos1 + 1 : L;
    const int qmax_warp = m0 + wid * 16 + 15;
    const int qmin_warp = m0 + wid * 16;

    for (int t = 0; t < ntiles; t++) {
        const int k0 = t * BN;
        asm volatile("cp.async.wait_group 0;" ::: "memory");
        __syncthreads();     // tile t visible; prior readers of other buffer done
        if (t + 1 < ntiles)
            prefetch_tile(smb, (t + 1) & 1, tid, hkv, start + k0 + BN, L, k0 + BN);
        asm volatile("cp.async.commit_group;" ::: "memory");

        if (k0 > qmax_warp) continue;   // fully-masked tile for this warp

        const uint32_t kh_b = smb + (uint32_t)((t & 1) * 32768);
        const uint32_t kl_b = kh_b + 8192;
        const uint32_t vh_b = kh_b + 16384;
        const uint32_t vl_b = kh_b + 24576;

        // ---- S = Q K^T (split bf16, 3 MMAs) ----
        float S[8][4];
        #pragma unroll
        for (int j = 0; j < 8; j++)
            #pragma unroll
            for (int e = 0; e < 4; e++) S[j][e] = 0.f;
        {
            int key = ((lane >> 4) & 1) * 8 + (lane & 7);
            int dhalf = ((lane >> 3) & 1) * 16;
            #pragma unroll
            for (int jp = 0; jp < 4; jp++) {
                #pragma unroll
                for (int kk = 0; kk < 4; kk++) {
                    uint32_t off = SW128((uint32_t)((16 * jp + key) * 128 + kk * 32 + dhalf));
                    uint32_t bh[4], bl[4];
                    ldsm_x4(bh, kh_b + off);
                    ldsm_x4(bl, kl_b + off);
                    mma16816(S[2*jp],   qh[kk], bh);
                    mma16816(S[2*jp],   qh[kk], bl);
                    mma16816(S[2*jp],   ql[kk], bh);
                    mma16816(S[2*jp+1], qh[kk], bh + 2);
                    mma16816(S[2*jp+1], qh[kk], bl + 2);
                    mma16816(S[2*jp+1], ql[kk], bh + 2);
                }
            }
        }

        // ---- causal mask + online softmax ----
        const bool full = (k0 + BN <= L) && (k0 + BN <= qmin_warp + 1);
        float tmax0 = -1e30f, tmax1 = -1e30f;
        if (full) {
            #pragma unroll
            for (int j = 0; j < 8; j++) {
                tmax0 = fmaxf(tmax0, fmaxf(S[j][0], S[j][1]));
                tmax1 = fmaxf(tmax1, fmaxf(S[j][2], S[j][3]));
            }
        } else {
            const int jm0 = klim0 - k0, jm1 = klim1 - k0;
            #pragma unroll
            for (int j = 0; j < 8; j++) {
                int kg = 8 * j + 2 * (lane & 3);
                S[j][0] = (kg     < jm0) ? S[j][0] : -1e30f;
                S[j][1] = (kg + 1 < jm0) ? S[j][1] : -1e30f;
                S[j][2] = (kg     < jm1) ? S[j][2] : -1e30f;
                S[j][3] = (kg + 1 < jm1) ? S[j][3] : -1e30f;
                tmax0 = fmaxf(tmax0, fmaxf(S[j][0], S[j][1]));
                tmax1 = fmaxf(tmax1, fmaxf(S[j][2], S[j][3]));
            }
        }
        tmax0 = fmaxf(tmax0, __shfl_xor_sync(0xffffffffu, tmax0, 1));
        tmax0 = fmaxf(tmax0, __shfl_xor_sync(0xffffffffu, tmax0, 2));
        tmax1 = fmaxf(tmax1, __shfl_xor_sync(0xffffffffu, tmax1, 1));
        tmax1 = fmaxf(tmax1, __shfl_xor_sync(0xffffffffu, tmax1, 2));

        float mnew0 = fmaxf(mrow0, tmax0);
        float mnew1 = fmaxf(mrow1, tmax1);
        float corr0 = ex2(mrow0 - mnew0);
        float corr1 = ex2(mrow1 - mnew1);
        mrow0 = mnew0; mrow1 = mnew1;
        lrow0 *= corr0; lrow1 *= corr1;
        #pragma unroll
        for (int j = 0; j < 8; j++) {
            O[j][0] *= corr0; O[j][1] *= corr0;
            O[j][2] *= corr1; O[j][3] *= corr1;
        }
        float ls0 = 0.f, ls1 = 0.f;
        #pragma unroll
        for (int j = 0; j < 8; j++) {
            S[j][0] = ex2(S[j][0] - mnew0);
            S[j][1] = ex2(S[j][1] - mnew0);
            S[j][2] = ex2(S[j][2] - mnew1);
            S[j][3] = ex2(S[j][3] - mnew1);
            ls0 += S[j][0] + S[j][1];
            ls1 += S[j][2] + S[j][3];
        }
        lrow0 += ls0; lrow1 += ls1;

        // ---- O += P V (split bf16, 3 MMAs), P frags from S in registers ----
        {
            int vkey = (lane & 15);
            int dhalf = ((lane >> 4) & 1) * 16;
            #pragma unroll
            for (int kk = 0; kk < 4; kk++) {
                uint32_t ph[4], pl[4];
                splitp(S[2*kk][0],   S[2*kk][1],   ph[0], pl[0]);
                splitp(S[2*kk][2],   S[2*kk][3],   ph[1], pl[1]);
                splitp(S[2*kk+1][0], S[2*kk+1][1], ph[2], pl[2]);
                splitp(S[2*kk+1][2], S[2*kk+1][3], ph[3], pl[3]);
                #pragma unroll
                for (int jp = 0; jp < 4; jp++) {
                    uint32_t off = SW128((uint32_t)((16 * kk + vkey) * 128 + jp * 32 + dhalf));
                    uint32_t bh[4], bl[4];
                    ldsm_x4t(bh, vh_b + off);
                    ldsm_x4t(bl, vl_b + off);
                    mma16816(O[2*jp],   ph, bh);
                    mma16816(O[2*jp],   ph, bl);
                    mma16816(O[2*jp],   pl, bh);
                    mma16816(O[2*jp+1], ph, bh + 2);
                    mma16816(O[2*jp+1], ph, bl + 2);
                    mma16816(O[2*jp+1], pl, bh + 2);
                }
            }
        }
    }

    // ---- epilogue ----
    lrow0 += __shfl_xor_sync(0xffffffffu, lrow0, 1);
    lrow0 += __shfl_xor_sync(0xffffffffu, lrow0, 2);
    lrow1 += __shfl_xor_sync(0xffffffffu, lrow1, 1);
    lrow1 += __shfl_xor_sync(0xffffffffu, lrow1, 2);
    float inv0 = 1.f / lrow0;
    float inv1 = 1.f / lrow1;

    const int col = 2 * (lane & 3);
    if (qpos0 < L) {
        float* o0 = out + ((size_t)(start + qpos0) * HEADS + h) * DH;
        #pragma unroll
        for (int jd = 0; jd < 8; jd++)
            *reinterpret_cast<float2*>(o0 + 8 * jd + col) =
                make_float2(O[jd][0] * inv0, O[jd][1] * inv0);
    }
    if (qpos1 < L) {
        float* o1 = out + ((size_t)(start + qpos1) * HEADS + h) * DH;
        #pragma unroll
        for (int jd = 0; jd < 8; jd++)
            *reinterpret_cast<float2*>(o1 + 8 * jd + col) =
                make_float2(O[jd][2] * inv1, O[jd][3] * inv1);
    }
}

extern "C" void kernel_launch(void* const* d_in, const int* in_sizes, int n_in,
                              void* d_out, int out_size)
{
    const float* q  = (const float*)d_in[0];
    const float* kv = (const float*)d_in[1];
    const int*   cu = (const int*)d_in[2];
    const int total   = in_sizes[0] / (HEADS * DH);
    const int nseq    = in_sizes[2] - 1;
    const int mblocks = (total + BM - 1) / BM;

    const int nitems = total * HKV * 32;
    convert_kv_kernel<<<(nitems + 255) / 256, 256>>>(kv, nitems);

    static int smem_set = 0;
    if (!smem_set) {
        cudaFuncSetAttribute(varlen_attn_hmma2,
                             cudaFuncAttributeMaxDynamicSharedMemorySize, 65536);
        smem_set = 1;
    }
    dim3 grid(mblocks, nseq, HEADS);
    varlen_attn_hmma2<<<grid, NTH, 65536>>>(q, cu, (float*)d_out);
}

// round 5
// speedup vs baseline: 7.3146x; 1.3067x over previous
#include <cuda_runtime.h>
#include <cuda_fp16.h>
#include <cstdint>

#define HEADS 16
#define HKV   4
#define DH    64
#define BM    128
#define BN    64
#define NTH   256
#define TMAX  8192

#define SW128(x) ((x) ^ (((x) >> 3) & 0x70))

// fp16 KV planes: 0=K, 1=V  [hkv][token][dim]
__device__ __align__(16) __half g_kvh[2][HKV][TMAX][DH];

__device__ __forceinline__ uint32_t smem_u32(const void* p) {
    uint32_t a;
    asm("{ .reg .u64 t; cvta.to.shared.u64 t, %1; cvt.u32.u64 %0, t; }"
        : "=r"(a) : "l"(p));
    return a;
}

__device__ __forceinline__ float ex2(float x) {
    float y; asm("ex2.approx.f32 %0, %1;" : "=f"(y) : "f"(x)); return y;
}

__device__ __forceinline__ void ldsm_x4(uint32_t* r, uint32_t addr) {
    asm volatile("ldmatrix.sync.aligned.m8n8.x4.shared.b16 {%0,%1,%2,%3}, [%4];"
        : "=r"(r[0]), "=r"(r[1]), "=r"(r[2]), "=r"(r[3]) : "r"(addr));
}
__device__ __forceinline__ void ldsm_x4t(uint32_t* r, uint32_t addr) {
    asm volatile("ldmatrix.sync.aligned.m8n8.x4.trans.shared.b16 {%0,%1,%2,%3}, [%4];"
        : "=r"(r[0]), "=r"(r[1]), "=r"(r[2]), "=r"(r[3]) : "r"(addr));
}

__device__ __forceinline__ void mma16816(float* d, const uint32_t* a, const uint32_t* b) {
    asm volatile("mma.sync.aligned.m16n8k16.row.col.f32.f16.f16.f32 "
        "{%0,%1,%2,%3}, {%4,%5,%6,%7}, {%8,%9}, {%0,%1,%2,%3};"
        : "+f"(d[0]), "+f"(d[1]), "+f"(d[2]), "+f"(d[3])
        : "r"(a[0]), "r"(a[1]), "r"(a[2]), "r"(a[3]), "r"(b[0]), "r"(b[1]));
}

__device__ __forceinline__ uint32_t packh(float x0, float x1) {
    uint32_t r; asm("cvt.rn.f16x2.f32 %0, %1, %2;" : "=r"(r) : "f"(x1), "f"(x0));
    return r;
}
// fp16 split: hi = rn(x), lo = rn(x - hi)
__device__ __forceinline__ void splitp(float x0, float x1, uint32_t& hi, uint32_t& lo) {
    hi = packh(x0, x1);
    __half2 h2 = *reinterpret_cast<__half2*>(&hi);
    lo = packh(x0 - __low2float(h2), x1 - __high2float(h2));
}

// ---------------- pre-pass: fp32 KV -> fp16 planes ----------------
__global__ void convert_kv_kernel(const float* __restrict__ kv, int nitems) {
    int idx = blockIdx.x * blockDim.x + threadIdx.x;
    if (idx >= nitems) return;               // nitems = total*HKV*32
    int c2  = idx & 31;
    int hk  = (idx >> 5) & 3;
    int tok = idx >> 7;
    const float* base = kv + (size_t)tok * (2 * HKV * DH) + hk * DH + 2 * c2;
    float2 kk = *reinterpret_cast<const float2*>(base);
    float2 vv = *reinterpret_cast<const float2*>(base + HKV * DH);
    *reinterpret_cast<uint32_t*>(&g_kvh[0][hk][tok][2 * c2]) = packh(kk.x, kk.y);
    *reinterpret_cast<uint32_t*>(&g_kvh[1][hk][tok][2 * c2]) = packh(vv.x, vv.y);
}

// cp.async one KV tile (K + V planes) into 16KB smem stage with SW128 swizzle
__device__ __forceinline__ void prefetch_tile(uint32_t smb, int buf, int tid,
                                              int hkv, int tok0, int L, int k0) {
    uint32_t dstb = smb + (uint32_t)buf * 16384u;
    #pragma unroll
    for (int p = 0; p < 2; p++) {
        const __half* plane = &g_kvh[p][hkv][0][0];
        #pragma unroll
        for (int i = 0; i < 2; i++) {
            int u   = i * NTH + tid;            // 512 granules of 16B per plane
            int key = u >> 3, g = u & 7;
            uint32_t dst = dstb + (uint32_t)p * 8192u
                         + SW128((uint32_t)(key * 128 + g * 16));
            const void* src = plane + (size_t)(tok0 + key) * DH + g * 8;
            unsigned n = (k0 + key < L) ? 16u : 0u;   // zfill OOB keys
            asm volatile("cp.async.cg.shared.global [%0], [%1], 16, %2;"
                         :: "r"(dst), "l"(src), "r"(n));
        }
    }
}

#define SMEM_DYN 81920   // 3x16KB KV stages + 2x16KB Q hi/lo staging

__global__ __launch_bounds__(NTH, 2) void varlen_attn_hmma3(
    const float* __restrict__ q,
    const int*   __restrict__ cu,
    float*       __restrict__ out)
{
    const int seq   = blockIdx.y;
    const int h     = blockIdx.z;
    const int start = cu[seq];
    const int L     = cu[seq + 1] - start;
    const int m0    = (gridDim.x - 1 - blockIdx.x) * BM;   // longest CTAs first
    if (m0 >= L) return;

    extern __shared__ uint8_t sm[];
    const uint32_t smb = smem_u32(sm);

    const int tid  = threadIdx.x;
    const int wid  = tid >> 5;
    const int lane = tid & 31;
    const int hkv  = h >> 2;
    const float SCALE = 0.125f * 1.4426950408889634f;

    const int klim_cta = (L < m0 + BM) ? L : (m0 + BM);
    const int ntiles   = (klim_cta + BN - 1) / BN;

    // prologue: stages for tiles 0 and 1
    prefetch_tile(smb, 0, tid, hkv, start, L, 0);
    asm volatile("cp.async.commit_group;" ::: "memory");

    // ---- stage Q (scaled, fp16 split hi/lo) ----
    #pragma unroll
    for (int it = 0; it < 16; it++) {
        int u = it * NTH + tid;
        int row = u >> 5, c2 = u & 31;
        float2 qv = make_float2(0.f, 0.f);
        if (m0 + row < L)
            qv = *reinterpret_cast<const float2*>(
                q + ((size_t)(start + m0 + row) * HEADS + h) * DH + 2 * c2);
        qv.x *= SCALE; qv.y *= SCALE;
        uint32_t hi, lo;
        splitp(qv.x, qv.y, hi, lo);
        uint32_t sw = SW128((uint32_t)(row * 128 + c2 * 4));
        *reinterpret_cast<uint32_t*>(sm + 49152 + sw) = hi;
        *reinterpret_cast<uint32_t*>(sm + 65536 + sw) = lo;
    }

    if (1 < ntiles)
        prefetch_tile(smb, 1, tid, hkv, start + BN, L, BN);
    asm volatile("cp.async.commit_group;" ::: "memory");
    __syncthreads();

    uint32_t qh[4][4], ql[4][4];
    {
        int qrow = wid * 16 + (lane & 15);
        #pragma unroll
        for (int kk = 0; kk < 4; kk++) {
            uint32_t off = SW128((uint32_t)(qrow * 128 + kk * 32 + ((lane >> 4) & 1) * 16));
            ldsm_x4(qh[kk], smb + 49152 + off);
            ldsm_x4(ql[kk], smb + 65536 + off);
        }
    }

    // ---- per-thread state ----
    float O[8][4];
    #pragma unroll
    for (int j = 0; j < 8; j++)
        #pragma unroll
        for (int e = 0; e < 4; e++) O[j][e] = 0.f;
    float mrow0 = -1e30f, mrow1 = -1e30f, lrow0 = 0.f, lrow1 = 0.f;

    const int qpos0 = m0 + wid * 16 + (lane >> 2);
    const int qpos1 = qpos0 + 8;
    const int klim0 = (qpos0 + 1 < L) ? qpos0 + 1 : L;
    const int klim1 = (qpos1 + 1 < L) ? qpos1 + 1 : L;
    const int qmax_warp = m0 + wid * 16 + 15;
    const int qmin_warp = m0 + wid * 16;

    int buf = 0;
    for (int t = 0; t < ntiles; t++, buf = (buf == 2) ? 0 : buf + 1) {
        const int k0 = t * BN;
        asm volatile("cp.async.wait_group 1;" ::: "memory");   // tile t landed
        __syncthreads();                                       // buf (t+2)%3 free
        if (t + 2 < ntiles)
            prefetch_tile(smb, (buf == 0) ? 2 : buf - 1, tid, hkv,
                          start + k0 + 2 * BN, L, k0 + 2 * BN);
        asm volatile("cp.async.commit_group;" ::: "memory");

        if (k0 > qmax_warp) continue;   // fully-masked tile for this warp

        const uint32_t kh_b = smb + (uint32_t)(buf * 16384);
        const uint32_t vh_b = kh_b + 8192;

        // ---- S = (Qh + Ql) * Kh  (2 MMAs per frag: exact-A, rounded-B) ----
        float S[8][4];
        #pragma unroll
        for (int j = 0; j < 8; j++)
            #pragma unroll
            for (int e = 0; e < 4; e++) S[j][e] = 0.f;
        {
            int key = ((lane >> 4) & 1) * 8 + (lane & 7);
            int dhalf = ((lane >> 3) & 1) * 16;
            #pragma unroll
            for (int jp = 0; jp < 4; jp++) {
                #pragma unroll
                for (int kk = 0; kk < 4; kk++) {
                    uint32_t off = SW128((uint32_t)((16 * jp + key) * 128 + kk * 32 + dhalf));
                    uint32_t bh[4];
                    ldsm_x4(bh, kh_b + off);
                    mma16816(S[2*jp],   qh[kk], bh);
                    mma16816(S[2*jp],   ql[kk], bh);
                    mma16816(S[2*jp+1], qh[kk], bh + 2);
                    mma16816(S[2*jp+1], ql[kk], bh + 2);
                }
            }
        }

        // ---- causal mask + online softmax ----
        const bool full = (k0 + BN <= L) && (k0 + BN <= qmin_warp + 1);
        float tmax0 = -1e30f, tmax1 = -1e30f;
        if (full) {
            #pragma unroll
            for (int j = 0; j < 8; j++) {
                tmax0 = fmaxf(tmax0, fmaxf(S[j][0], S[j][1]));
                tmax1 = fmaxf(tmax1, fmaxf(S[j][2], S[j][3]));
            }
        } else {
            const int jm0 = klim0 - k0, jm1 = klim1 - k0;
            #pragma unroll
            for (int j = 0; j < 8; j++) {
                int kg = 8 * j + 2 * (lane & 3);
                S[j][0] = (kg     < jm0) ? S[j][0] : -1e30f;
                S[j][1] = (kg + 1 < jm0) ? S[j][1] : -1e30f;
                S[j][2] = (kg     < jm1) ? S[j][2] : -1e30f;
                S[j][3] = (kg + 1 < jm1) ? S[j][3] : -1e30f;
                tmax0 = fmaxf(tmax0, fmaxf(S[j][0], S[j][1]));
                tmax1 = fmaxf(tmax1, fmaxf(S[j][2], S[j][3]));
            }
        }
        tmax0 = fmaxf(tmax0, __shfl_xor_sync(0xffffffffu, tmax0, 1));
        tmax0 = fmaxf(tmax0, __shfl_xor_sync(0xffffffffu, tmax0, 2));
        tmax1 = fmaxf(tmax1, __shfl_xor_sync(0xffffffffu, tmax1, 1));
        tmax1 = fmaxf(tmax1, __shfl_xor_sync(0xffffffffu, tmax1, 2));

        float mnew0 = fmaxf(mrow0, tmax0);
        float mnew1 = fmaxf(mrow1, tmax1);
        float corr0 = ex2(mrow0 - mnew0);
        float corr1 = ex2(mrow1 - mnew1);
        mrow0 = mnew0; mrow1 = mnew1;
        lrow0 *= corr0; lrow1 *= corr1;
        #pragma unroll
        for (int j = 0; j < 8; j++) {
            O[j][0] *= corr0; O[j][1] *= corr0;
            O[j][2] *= corr1; O[j][3] *= corr1;
        }
        float ls0 = 0.f, ls1 = 0.f;
        #pragma unroll
        for (int j = 0; j < 8; j++) {
            S[j][0] = ex2(S[j][0] - mnew0);
            S[j][1] = ex2(S[j][1] - mnew0);
            S[j][2] = ex2(S[j][2] - mnew1);
            S[j][3] = ex2(S[j][3] - mnew1);
            ls0 += S[j][0] + S[j][1];
            ls1 += S[j][2] + S[j][3];
        }
        lrow0 += ls0; lrow1 += ls1;

        // ---- O += (Ph + Pl) * Vh ----
        {
            int vkey = (lane & 15);
            int dhalf = ((lane >> 4) & 1) * 16;
            #pragma unroll
            for (int kk = 0; kk < 4; kk++) {
                uint32_t ph[4], pl[4];
                splitp(S[2*kk][0],   S[2*kk][1],   ph[0], pl[0]);
                splitp(S[2*kk][2],   S[2*kk][3],   ph[1], pl[1]);
                splitp(S[2*kk+1][0], S[2*kk+1][1], ph[2], pl[2]);
                splitp(S[2*kk+1][2], S[2*kk+1][3], ph[3], pl[3]);
                #pragma unroll
                for (int jp = 0; jp < 4; jp++) {
                    uint32_t off = SW128((uint32_t)((16 * kk + vkey) * 128 + jp * 32 + dhalf));
                    uint32_t bh[4];
                    ldsm_x4t(bh, vh_b + off);
                    mma16816(O[2*jp],   ph, bh);
                    mma16816(O[2*jp],   pl, bh);
                    mma16816(O[2*jp+1], ph, bh + 2);
                    mma16816(O[2*jp+1], pl, bh + 2);
                }
            }
        }
    }

    // ---- epilogue ----
    lrow0 += __shfl_xor_sync(0xffffffffu, lrow0, 1);
    lrow0 += __shfl_xor_sync(0xffffffffu, lrow0, 2);
    lrow1 += __shfl_xor_sync(0xffffffffu, lrow1, 1);
    lrow1 += __shfl_xor_sync(0xffffffffu, lrow1, 2);
    float inv0 = 1.f / lrow0;
    float inv1 = 1.f / lrow1;

    const int col = 2 * (lane & 3);
    if (qpos0 < L) {
        float* o0 = out + ((size_t)(start + qpos0) * HEADS + h) * DH;
        #pragma unroll
        for (int jd = 0; jd < 8; jd++)
            *reinterpret_cast<float2*>(o0 + 8 * jd + col) =
                make_float2(O[jd][0] * inv0, O[jd][1] * inv0);
    }
    if (qpos1 < L) {
        float* o1 = out + ((size_t)(start + qpos1) * HEADS + h) * DH;
        #pragma unroll
        for (int jd = 0; jd < 8; jd++)
            *reinterpret_cast<float2*>(o1 + 8 * jd + col) =
                make_float2(O[jd][2] * inv1, O[jd][3] * inv1);
    }
}

extern "C" void kernel_launch(void* const* d_in, const int* in_sizes, int n_in,
                              void* d_out, int out_size)
{
    const float* q  = (const float*)d_in[0];
    const float* kv = (const float*)d_in[1];
    const int*   cu = (const int*)d_in[2];
    const int total   = in_sizes[0] / (HEADS * DH);
    const int nseq    = in_sizes[2] - 1;
    const int mblocks = (total + BM - 1) / BM;

    const int nitems = total * HKV * 32;
    convert_kv_kernel<<<(nitems + 255) / 256, 256>>>(kv, nitems);

    static int smem_set = 0;
    if (!smem_set) {
        cudaFuncSetAttribute(varlen_attn_hmma3,
                             cudaFuncAttributeMaxDynamicSharedMemorySize, SMEM_DYN);
        smem_set = 1;
    }
    dim3 grid(mblocks, nseq, HEADS);
    varlen_attn_hmma3<<<grid, NTH, SMEM_DYN>>>(q, cu, (float*)d_out);
}

// round 6
// speedup vs baseline: 10.2955x; 1.4075x over previous
#include <cuda_runtime.h>
#include <cuda_fp16.h>
#include <cstdint>

#define HEADS 16
#define HKV   4
#define DH    64
#define BM    128
#define BN    64
#define NTH   256
#define TMAX  8192

#define SW128(x) ((x) ^ (((x) >> 3) & 0x70))

// fp16 KV planes: 0=K, 1=V  [hkv][token][dim]
__device__ __align__(16) __half g_kvh[2][HKV][TMAX][DH];

__device__ __forceinline__ uint32_t smem_u32(const void* p) {
    uint32_t a;
    asm("{ .reg .u64 t; cvta.to.shared.u64 t, %1; cvt.u32.u64 %0, t; }"
        : "=r"(a) : "l"(p));
    return a;
}

__device__ __forceinline__ float ex2(float x) {
    float y; asm("ex2.approx.f32 %0, %1;" : "=f"(y) : "f"(x)); return y;
}

__device__ __forceinline__ void ldsm_x4(uint32_t* r, uint32_t addr) {
    asm volatile("ldmatrix.sync.aligned.m8n8.x4.shared.b16 {%0,%1,%2,%3}, [%4];"
        : "=r"(r[0]), "=r"(r[1]), "=r"(r[2]), "=r"(r[3]) : "r"(addr));
}
__device__ __forceinline__ void ldsm_x4t(uint32_t* r, uint32_t addr) {
    asm volatile("ldmatrix.sync.aligned.m8n8.x4.trans.shared.b16 {%0,%1,%2,%3}, [%4];"
        : "=r"(r[0]), "=r"(r[1]), "=r"(r[2]), "=r"(r[3]) : "r"(addr));
}

__device__ __forceinline__ void mma16816(float* d, const uint32_t* a, const uint32_t* b) {
    asm volatile("mma.sync.aligned.m16n8k16.row.col.f32.f16.f16.f32 "
        "{%0,%1,%2,%3}, {%4,%5,%6,%7}, {%8,%9}, {%0,%1,%2,%3};"
        : "+f"(d[0]), "+f"(d[1]), "+f"(d[2]), "+f"(d[3])
        : "r"(a[0]), "r"(a[1]), "r"(a[2]), "r"(a[3]), "r"(b[0]), "r"(b[1]));
}

__device__ __forceinline__ uint32_t packh(float x0, float x1) {
    uint32_t r; asm("cvt.rn.f16x2.f32 %0, %1, %2;" : "=r"(r) : "f"(x1), "f"(x0));
    return r;
}

// ---------------- pre-pass: fp32 KV -> fp16 planes ----------------
__global__ void convert_kv_kernel(const float* __restrict__ kv, int nitems) {
    int idx = blockIdx.x * blockDim.x + threadIdx.x;
    if (idx >= nitems) return;               // nitems = total*HKV*32
    int c2  = idx & 31;
    int hk  = (idx >> 5) & 3;
    int tok = idx >> 7;
    const float* base = kv + (size_t)tok * (2 * HKV * DH) + hk * DH + 2 * c2;
    float2 kk = *reinterpret_cast<const float2*>(base);
    float2 vv = *reinterpret_cast<const float2*>(base + HKV * DH);
    *reinterpret_cast<uint32_t*>(&g_kvh[0][hk][tok][2 * c2]) = packh(kk.x, kk.y);
    *reinterpret_cast<uint32_t*>(&g_kvh[1][hk][tok][2 * c2]) = packh(vv.x, vv.y);
}

// cp.async one KV tile (K + V planes) into 16KB smem stage with SW128 swizzle
__device__ __forceinline__ void prefetch_tile(uint32_t smb, int buf, int tid,
                                              int hkv, int tok0, int L, int k0) {
    uint32_t dstb = smb + (uint32_t)buf * 16384u;
    #pragma unroll
    for (int p = 0; p < 2; p++) {
        const __half* plane = &g_kvh[p][hkv][0][0];
        #pragma unroll
        for (int i = 0; i < 2; i++) {
            int u   = i * NTH + tid;            // 512 granules of 16B per plane
            int key = u >> 3, g = u & 7;
            uint32_t dst = dstb + (uint32_t)p * 8192u
                         + SW128((uint32_t)(key * 128 + g * 16));
            const void* src = plane + (size_t)(tok0 + key) * DH + g * 8;
            unsigned n = (k0 + key < L) ? 16u : 0u;   // zfill OOB keys
            asm volatile("cp.async.cg.shared.global [%0], [%1], 16, %2;"
                         :: "r"(dst), "l"(src), "r"(n));
        }
    }
}

#define SMEM_DYN 65536   // 3x16KB KV stages + 16KB Q staging

__global__ __launch_bounds__(NTH, 2) void varlen_attn_hmma4(
    const float* __restrict__ q,
    const int*   __restrict__ cu,
    float*       __restrict__ out)
{
    const int seq   = blockIdx.y;
    const int h     = blockIdx.z;
    const int start = cu[seq];
    const int L     = cu[seq + 1] - start;
    const int m0    = (gridDim.x - 1 - blockIdx.x) * BM;   // longest CTAs first
    if (m0 >= L) return;

    extern __shared__ uint8_t sm[];
    const uint32_t smb = smem_u32(sm);

    const int tid  = threadIdx.x;
    const int wid  = tid >> 5;
    const int lane = tid & 31;
    const int hkv  = h >> 2;
    const float SCALE = 0.125f * 1.4426950408889634f;

    const int klim_cta = (L < m0 + BM) ? L : (m0 + BM);
    const int ntiles   = (klim_cta + BN - 1) / BN;

    // prologue: stages for tiles 0 and 1
    prefetch_tile(smb, 0, tid, hkv, start, L, 0);
    asm volatile("cp.async.commit_group;" ::: "memory");

    // ---- stage Q (scaled, fp16) ----
    #pragma unroll
    for (int it = 0; it < 16; it++) {
        int u = it * NTH + tid;
        int row = u >> 5, c2 = u & 31;
        float2 qv = make_float2(0.f, 0.f);
        if (m0 + row < L)
            qv = *reinterpret_cast<const float2*>(
                q + ((size_t)(start + m0 + row) * HEADS + h) * DH + 2 * c2);
        uint32_t sw = SW128((uint32_t)(row * 128 + c2 * 4));
        *reinterpret_cast<uint32_t*>(sm + 49152 + sw) = packh(qv.x * SCALE, qv.y * SCALE);
    }

    if (1 < ntiles)
        prefetch_tile(smb, 1, tid, hkv, start + BN, L, BN);
    asm volatile("cp.async.commit_group;" ::: "memory");
    __syncthreads();

    uint32_t qh[4][4];
    {
        int qrow = wid * 16 + (lane & 15);
        #pragma unroll
        for (int kk = 0; kk < 4; kk++) {
            uint32_t off = SW128((uint32_t)(qrow * 128 + kk * 32 + ((lane >> 4) & 1) * 16));
            ldsm_x4(qh[kk], smb + 49152 + off);
        }
    }

    // ---- per-thread state ----
    float O[8][4];
    #pragma unroll
    for (int j = 0; j < 8; j++)
        #pragma unroll
        for (int e = 0; e < 4; e++) O[j][e] = 0.f;
    float mrow0 = -1e30f, mrow1 = -1e30f, lrow0 = 0.f, lrow1 = 0.f;

    const int qpos0 = m0 + wid * 16 + (lane >> 2);
    const int qpos1 = qpos0 + 8;
    const int klim0 = (qpos0 + 1 < L) ? qpos0 + 1 : L;
    const int klim1 = (qpos1 + 1 < L) ? qpos1 + 1 : L;
    const int qmax_warp = m0 + wid * 16 + 15;
    const int qmin_warp = m0 + wid * 16;

    int buf = 0;
    for (int t = 0; t < ntiles; t++, buf = (buf == 2) ? 0 : buf + 1) {
        const int k0 = t * BN;
        asm volatile("cp.async.wait_group 1;" ::: "memory");   // tile t landed
        __syncthreads();                                       // buf (t+2)%3 free
        if (t + 2 < ntiles)
            prefetch_tile(smb, (buf == 0) ? 2 : buf - 1, tid, hkv,
                          start + k0 + 2 * BN, L, k0 + 2 * BN);
        asm volatile("cp.async.commit_group;" ::: "memory");

        if (k0 > qmax_warp) continue;   // fully-masked tile for this warp

        const uint32_t kh_b = smb + (uint32_t)(buf * 16384);
        const uint32_t vh_b = kh_b + 8192;

        // ---- S = Q * K^T ----
        float S[8][4];
        #pragma unroll
        for (int j = 0; j < 8; j++)
            #pragma unroll
            for (int e = 0; e < 4; e++) S[j][e] = 0.f;
        {
            int key = ((lane >> 4) & 1) * 8 + (lane & 7);
            int dhalf = ((lane >> 3) & 1) * 16;
            #pragma unroll
            for (int jp = 0; jp < 4; jp++) {
                #pragma unroll
                for (int kk = 0; kk < 4; kk++) {
                    uint32_t off = SW128((uint32_t)((16 * jp + key) * 128 + kk * 32 + dhalf));
                    uint32_t bh[4];
                    ldsm_x4(bh, kh_b + off);
                    mma16816(S[2*jp],   qh[kk], bh);
                    mma16816(S[2*jp+1], qh[kk], bh + 2);
                }
            }
        }

        // ---- causal mask + online softmax ----
        const bool full = (k0 + BN <= L) && (k0 + BN <= qmin_warp + 1);
        float tmax0 = -1e30f, tmax1 = -1e30f;
        if (full) {
            #pragma unroll
            for (int j = 0; j < 8; j++) {
                tmax0 = fmaxf(tmax0, fmaxf(S[j][0], S[j][1]));
                tmax1 = fmaxf(tmax1, fmaxf(S[j][2], S[j][3]));
            }
        } else {
            const int jm0 = klim0 - k0, jm1 = klim1 - k0;
            #pragma unroll
            for (int j = 0; j < 8; j++) {
                int kg = 8 * j + 2 * (lane & 3);
                S[j][0] = (kg     < jm0) ? S[j][0] : -1e30f;
                S[j][1] = (kg + 1 < jm0) ? S[j][1] : -1e30f;
                S[j][2] = (kg     < jm1) ? S[j][2] : -1e30f;
                S[j][3] = (kg + 1 < jm1) ? S[j][3] : -1e30f;
                tmax0 = fmaxf(tmax0, fmaxf(S[j][0], S[j][1]));
                tmax1 = fmaxf(tmax1, fmaxf(S[j][2], S[j][3]));
            }
        }
        tmax0 = fmaxf(tmax0, __shfl_xor_sync(0xffffffffu, tmax0, 1));
        tmax0 = fmaxf(tmax0, __shfl_xor_sync(0xffffffffu, tmax0, 2));
        tmax1 = fmaxf(tmax1, __shfl_xor_sync(0xffffffffu, tmax1, 1));
        tmax1 = fmaxf(tmax1, __shfl_xor_sync(0xffffffffu, tmax1, 2));

        float mnew0 = fmaxf(mrow0, tmax0);
        float mnew1 = fmaxf(mrow1, tmax1);
        float corr0 = ex2(mrow0 - mnew0);
        float corr1 = ex2(mrow1 - mnew1);
        mrow0 = mnew0; mrow1 = mnew1;
        lrow0 *= corr0; lrow1 *= corr1;
        #pragma unroll
        for (int j = 0; j < 8; j++) {
            O[j][0] *= corr0; O[j][1] *= corr0;
            O[j][2] *= corr1; O[j][3] *= corr1;
        }
        float ls0 = 0.f, ls1 = 0.f;
        #pragma unroll
        for (int j = 0; j < 8; j++) {
            S[j][0] = ex2(S[j][0] - mnew0);
            S[j][1] = ex2(S[j][1] - mnew0);
            S[j][2] = ex2(S[j][2] - mnew1);
            S[j][3] = ex2(S[j][3] - mnew1);
            ls0 += S[j][0] + S[j][1];
            ls1 += S[j][2] + S[j][3];
        }
        lrow0 += ls0; lrow1 += ls1;

        // ---- O += P * V  (P packed fp16 straight from S) ----
        {
            int vkey = (lane & 15);
            int dhalf = ((lane >> 4) & 1) * 16;
            #pragma unroll
            for (int kk = 0; kk < 4; kk++) {
                uint32_t ph[4];
                ph[0] = packh(S[2*kk][0],   S[2*kk][1]);
                ph[1] = packh(S[2*kk][2],   S[2*kk][3]);
                ph[2] = packh(S[2*kk+1][0], S[2*kk+1][1]);
                ph[3] = packh(S[2*kk+1][2], S[2*kk+1][3]);
                #pragma unroll
                for (int jp = 0; jp < 4; jp++) {
                    uint32_t off = SW128((uint32_t)((16 * kk + vkey) * 128 + jp * 32 + dhalf));
                    uint32_t bh[4];
                    ldsm_x4t(bh, vh_b + off);
                    mma16816(O[2*jp],   ph, bh);
                    mma16816(O[2*jp+1], ph, bh + 2);
                }
            }
        }
    }

    // ---- epilogue ----
    lrow0 += __shfl_xor_sync(0xffffffffu, lrow0, 1);
    lrow0 += __shfl_xor_sync(0xffffffffu, lrow0, 2);
    lrow1 += __shfl_xor_sync(0xffffffffu, lrow1, 1);
    lrow1 += __shfl_xor_sync(0xffffffffu, lrow1, 2);
    float inv0 = 1.f / lrow0;
    float inv1 = 1.f / lrow1;

    const int col = 2 * (lane & 3);
    if (qpos0 < L) {
        float* o0 = out + ((size_t)(start + qpos0) * HEADS + h) * DH;
        #pragma unroll
        for (int jd = 0; jd < 8; jd++)
            *reinterpret_cast<float2*>(o0 + 8 * jd + col) =
                make_float2(O[jd][0] * inv0, O[jd][1] * inv0);
    }
    if (qpos1 < L) {
        float* o1 = out + ((size_t)(start + qpos1) * HEADS + h) * DH;
        #pragma unroll
        for (int jd = 0; jd < 8; jd++)
            *reinterpret_cast<float2*>(o1 + 8 * jd + col) =
                make_float2(O[jd][2] * inv1, O[jd][3] * inv1);
    }
}

extern "C" void kernel_launch(void* const* d_in, const int* in_sizes, int n_in,
                              void* d_out, int out_size)
{
    const float* q  = (const float*)d_in[0];
    const float* kv = (const float*)d_in[1];
    const int*   cu = (const int*)d_in[2];
    const int total   = in_sizes[0] / (HEADS * DH);
    const int nseq    = in_sizes[2] - 1;
    const int mblocks = (total + BM - 1) / BM;

    const int nitems = total * HKV * 32;
    convert_kv_kernel<<<(nitems + 255) / 256, 256>>>(kv, nitems);

    static int smem_set = 0;
    if (!smem_set) {
        cudaFuncSetAttribute(varlen_attn_hmma4,
                             cudaFuncAttributeMaxDynamicSharedMemorySize, SMEM_DYN);
        smem_set = 1;
    }
    dim3 grid(mblocks, nseq, HEADS);
    varlen_attn_hmma4<<<grid, NTH, SMEM_DYN>>>(q, cu, (float*)d_out);
}

// round 7
// speedup vs baseline: 11.3415x; 1.1016x over previous
#include <cuda_runtime.h>
#include <cuda_fp16.h>
#include <cstdint>

#define HEADS 16
#define HKV   4
#define DH    64
#define BM    128
#define BN    64
#define NTH   256
#define TMAX  8192

#define SW128(x) ((x) ^ (((x) >> 3) & 0x70))

// fp16 KV planes: 0=K, 1=V  [hkv][token][dim]
__device__ __align__(16) __half g_kvh[2][HKV][TMAX][DH];

__device__ __forceinline__ uint32_t smem_u32(const void* p) {
    uint32_t a;
    asm("{ .reg .u64 t; cvta.to.shared.u64 t, %1; cvt.u32.u64 %0, t; }"
        : "=r"(a) : "l"(p));
    return a;
}

__device__ __forceinline__ float ex2(float x) {
    float y; asm("ex2.approx.f32 %0, %1;" : "=f"(y) : "f"(x)); return y;
}
__device__ __forceinline__ uint32_t ex2h2(uint32_t x) {
    uint32_t r; asm("ex2.approx.f16x2 %0, %1;" : "=r"(r) : "r"(x)); return r;
}
__device__ __forceinline__ uint32_t hmax2u(uint32_t a, uint32_t b) {
    uint32_t r; asm("max.f16x2 %0, %1, %2;" : "=r"(r) : "r"(a), "r"(b)); return r;
}
__device__ __forceinline__ uint32_t hsub2u(uint32_t a, uint32_t b) {
    uint32_t r; asm("sub.f16x2 %0, %1, %2;" : "=r"(r) : "r"(a), "r"(b)); return r;
}

__device__ __forceinline__ void ldsm_x4(uint32_t* r, uint32_t addr) {
    asm volatile("ldmatrix.sync.aligned.m8n8.x4.shared.b16 {%0,%1,%2,%3}, [%4];"
        : "=r"(r[0]), "=r"(r[1]), "=r"(r[2]), "=r"(r[3]) : "r"(addr));
}
__device__ __forceinline__ void ldsm_x4t(uint32_t* r, uint32_t addr) {
    asm volatile("ldmatrix.sync.aligned.m8n8.x4.trans.shared.b16 {%0,%1,%2,%3}, [%4];"
        : "=r"(r[0]), "=r"(r[1]), "=r"(r[2]), "=r"(r[3]) : "r"(addr));
}

__device__ __forceinline__ void mma16816(float* d, const uint32_t* a, const uint32_t* b) {
    asm volatile("mma.sync.aligned.m16n8k16.row.col.f32.f16.f16.f32 "
        "{%0,%1,%2,%3}, {%4,%5,%6,%7}, {%8,%9}, {%0,%1,%2,%3};"
        : "+f"(d[0]), "+f"(d[1]), "+f"(d[2]), "+f"(d[3])
        : "r"(a[0]), "r"(a[1]), "r"(a[2]), "r"(a[3]), "r"(b[0]), "r"(b[1]));
}

__device__ __forceinline__ uint32_t packh(float x0, float x1) {
    uint32_t r; asm("cvt.rn.f16x2.f32 %0, %1, %2;" : "=r"(r) : "f"(x1), "f"(x0));
    return r;
}

// ---------------- pre-pass: fp32 KV -> fp16 planes ----------------
__global__ void convert_kv_kernel(const float* __restrict__ kv, int nitems) {
    int idx = blockIdx.x * blockDim.x + threadIdx.x;
    if (idx >= nitems) return;               // nitems = total*HKV*32
    int c2  = idx & 31;
    int hk  = (idx >> 5) & 3;
    int tok = idx >> 7;
    const float* base = kv + (size_t)tok * (2 * HKV * DH) + hk * DH + 2 * c2;
    float2 kk = *reinterpret_cast<const float2*>(base);
    float2 vv = *reinterpret_cast<const float2*>(base + HKV * DH);
    *reinterpret_cast<uint32_t*>(&g_kvh[0][hk][tok][2 * c2]) = packh(kk.x, kk.y);
    *reinterpret_cast<uint32_t*>(&g_kvh[1][hk][tok][2 * c2]) = packh(vv.x, vv.y);
}

// cp.async one KV tile (K + V planes) into 16KB smem stage with SW128 swizzle
__device__ __forceinline__ void prefetch_tile(uint32_t smb, int buf, int tid,
                                              int hkv, int tok0, int L, int k0) {
    uint32_t dstb = smb + (uint32_t)buf * 16384u;
    #pragma unroll
    for (int p = 0; p < 2; p++) {
        const __half* plane = &g_kvh[p][hkv][0][0];
        #pragma unroll
        for (int i = 0; i < 2; i++) {
            int u   = i * NTH + tid;            // 512 granules of 16B per plane
            int key = u >> 3, g = u & 7;
            uint32_t dst = dstb + (uint32_t)p * 8192u
                         + SW128((uint32_t)(key * 128 + g * 16));
            const void* src = plane + (size_t)(tok0 + key) * DH + g * 8;
            unsigned n = (k0 + key < L) ? 16u : 0u;   // zfill OOB keys
            asm volatile("cp.async.cg.shared.global [%0], [%1], 16, %2;"
                         :: "r"(dst), "l"(src), "r"(n));
        }
    }
}

#define SMEM_DYN 65536   // 3x16KB KV stages + 16KB Q staging

__global__ __launch_bounds__(NTH, 2) void varlen_attn_hmma5(
    const float* __restrict__ q,
    const int*   __restrict__ cu,
    float*       __restrict__ out)
{
    const int seq   = blockIdx.y;
    const int h     = blockIdx.z;
    const int start = cu[seq];
    const int L     = cu[seq + 1] - start;
    const int m0    = (gridDim.x - 1 - blockIdx.x) * BM;   // longest CTAs first
    if (m0 >= L) return;

    extern __shared__ uint8_t sm[];
    const uint32_t smb = smem_u32(sm);

    const int tid  = threadIdx.x;
    const int wid  = tid >> 5;
    const int lane = tid & 31;
    const int hkv  = h >> 2;
    const float SCALE = 0.125f * 1.4426950408889634f;

    const int klim_cta = (L < m0 + BM) ? L : (m0 + BM);
    const int ntiles   = (klim_cta + BN - 1) / BN;

    // prologue: stages for tiles 0 and 1
    prefetch_tile(smb, 0, tid, hkv, start, L, 0);
    asm volatile("cp.async.commit_group;" ::: "memory");

    // ---- stage Q (scaled, fp16) ----
    #pragma unroll
    for (int it = 0; it < 16; it++) {
        int u = it * NTH + tid;
        int row = u >> 5, c2 = u & 31;
        float2 qv = make_float2(0.f, 0.f);
        if (m0 + row < L)
            qv = *reinterpret_cast<const float2*>(
                q + ((size_t)(start + m0 + row) * HEADS + h) * DH + 2 * c2);
        uint32_t sw = SW128((uint32_t)(row * 128 + c2 * 4));
        *reinterpret_cast<uint32_t*>(sm + 49152 + sw) = packh(qv.x * SCALE, qv.y * SCALE);
    }

    if (1 < ntiles)
        prefetch_tile(smb, 1, tid, hkv, start + BN, L, BN);
    asm volatile("cp.async.commit_group;" ::: "memory");
    __syncthreads();

    uint32_t qh[4][4];
    {
        int qrow = wid * 16 + (lane & 15);
        #pragma unroll
        for (int kk = 0; kk < 4; kk++) {
            uint32_t off = SW128((uint32_t)(qrow * 128 + kk * 32 + ((lane >> 4) & 1) * 16));
            ldsm_x4(qh[kk], smb + 49152 + off);
        }
    }

    // ---- per-thread state ----
    float O[8][4];
    #pragma unroll
    for (int j = 0; j < 8; j++)
        #pragma unroll
        for (int e = 0; e < 4; e++) O[j][e] = 0.f;
    float l2[4] = {0.f, 0.f, 0.f, 0.f};      // MMA accumulator: l0 in [0], l1 in [2]
    float mrow0 = -1e30f, mrow1 = -1e30f;

    const int qpos0 = m0 + wid * 16 + (lane >> 2);
    const int qpos1 = qpos0 + 8;
    const int klim0 = (qpos0 + 1 < L) ? qpos0 + 1 : L;
    const int klim1 = (qpos1 + 1 < L) ? qpos1 + 1 : L;
    const int qmax_warp = m0 + wid * 16 + 15;
    const int qmin_warp = m0 + wid * 16;

    const uint32_t ones2[2] = {0x3C003C00u, 0x3C003C00u};   // fp16 1.0 pair

    int buf = 0;
    for (int t = 0; t < ntiles; t++, buf = (buf == 2) ? 0 : buf + 1) {
        const int k0 = t * BN;
        asm volatile("cp.async.wait_group 1;" ::: "memory");   // tile t landed
        __syncthreads();                                       // buf (t+2)%3 free
        if (t + 2 < ntiles)
            prefetch_tile(smb, (buf == 0) ? 2 : buf - 1, tid, hkv,
                          start + k0 + 2 * BN, L, k0 + 2 * BN);
        asm volatile("cp.async.commit_group;" ::: "memory");

        if (k0 > qmax_warp) continue;   // fully-masked tile for this warp

        const uint32_t kh_b = smb + (uint32_t)(buf * 16384);
        const uint32_t vh_b = kh_b + 8192;

        // ---- S = Q * K^T ----
        float S[8][4];
        #pragma unroll
        for (int j = 0; j < 8; j++)
            #pragma unroll
            for (int e = 0; e < 4; e++) S[j][e] = 0.f;
        {
            int key = ((lane >> 4) & 1) * 8 + (lane & 7);
            int dhalf = ((lane >> 3) & 1) * 16;
            #pragma unroll
            for (int jp = 0; jp < 4; jp++) {
                #pragma unroll
                for (int kk = 0; kk < 4; kk++) {
                    uint32_t off = SW128((uint32_t)((16 * jp + key) * 128 + kk * 32 + dhalf));
                    uint32_t bh[4];
                    ldsm_x4(bh, kh_b + off);
                    mma16816(S[2*jp],   qh[kk], bh);
                    mma16816(S[2*jp+1], qh[kk], bh + 2);
                }
            }
        }

        // ---- pack scores to f16x2 rows (mask in fp32 on edge tiles) ----
        uint32_t h0[8], h1[8];   // h0 = row-group0 pairs, h1 = row-group1
        const bool full = (k0 + BN <= L) && (k0 + BN <= qmin_warp + 1);
        if (full) {
            #pragma unroll
            for (int j = 0; j < 8; j++) {
                h0[j] = packh(S[j][0], S[j][1]);
                h1[j] = packh(S[j][2], S[j][3]);
            }
        } else {
            const int jm0 = klim0 - k0, jm1 = klim1 - k0;
            #pragma unroll
            for (int j = 0; j < 8; j++) {
                int kg = 8 * j + 2 * (lane & 3);
                float a0 = (kg     < jm0) ? S[j][0] : -1e30f;  // -> -inf in fp16
                float a1 = (kg + 1 < jm0) ? S[j][1] : -1e30f;
                float a2 = (kg     < jm1) ? S[j][2] : -1e30f;
                float a3 = (kg + 1 < jm1) ? S[j][3] : -1e30f;
                h0[j] = packh(a0, a1);
                h1[j] = packh(a2, a3);
            }
        }

        // ---- tile max (f16x2 tree + packed quad shuffles) ----
        uint32_t t0 = hmax2u(hmax2u(hmax2u(h0[0], h0[1]), hmax2u(h0[2], h0[3])),
                             hmax2u(hmax2u(h0[4], h0[5]), hmax2u(h0[6], h0[7])));
        uint32_t t1 = hmax2u(hmax2u(hmax2u(h1[0], h1[1]), hmax2u(h1[2], h1[3])),
                             hmax2u(hmax2u(h1[4], h1[5]), hmax2u(h1[6], h1[7])));
        uint32_t tm;
        {
            __half2 a = *reinterpret_cast<__half2*>(&t0);
            __half2 b = *reinterpret_cast<__half2*>(&t1);
            __half2 c = __halves2half2(__hmax(__low2half(a), __high2half(a)),
                                       __hmax(__low2half(b), __high2half(b)));
            tm = *reinterpret_cast<uint32_t*>(&c);
        }
        tm = hmax2u(tm, __shfl_xor_sync(0xffffffffu, tm, 1));
        tm = hmax2u(tm, __shfl_xor_sync(0xffffffffu, tm, 2));
        __half2 tmh = *reinterpret_cast<__half2*>(&tm);

        // mnew rounded to fp16 so p / corr / l / O all share one constant
        float mnew0 = fmaxf(mrow0, __low2float(tmh));
        float mnew1 = fmaxf(mrow1, __high2float(tmh));
        __half mn0 = __float2half_rn(mnew0);
        __half mn1 = __float2half_rn(mnew1);
        mnew0 = __half2float(mn0);
        mnew1 = __half2float(mn1);
        float corr0 = ex2(mrow0 - mnew0);   // 0 on first tile
        float corr1 = ex2(mrow1 - mnew1);
        mrow0 = mnew0; mrow1 = mnew1;
        l2[0] *= corr0; l2[2] *= corr1;
        #pragma unroll
        for (int j = 0; j < 8; j++) {
            O[j][0] *= corr0; O[j][1] *= corr0;
            O[j][2] *= corr1; O[j][3] *= corr1;
        }

        // ---- P = exp2(S - m) in f16x2 (already packed for MMA) ----
        uint32_t m00, m11;
        {
            __half2 x = __half2half2(mn0);
            __half2 y = __half2half2(mn1);
            m00 = *reinterpret_cast<uint32_t*>(&x);
            m11 = *reinterpret_cast<uint32_t*>(&y);
        }
        #pragma unroll
        for (int j = 0; j < 8; j++) {
            h0[j] = ex2h2(hsub2u(h0[j], m00));
            h1[j] = ex2h2(hsub2u(h1[j], m11));
        }

        // ---- l += P * ones (tensor pipe, exact fp32 row-sums) ----
        #pragma unroll
        for (int kk = 0; kk < 4; kk++) {
            uint32_t a[4] = {h0[2*kk], h1[2*kk], h0[2*kk+1], h1[2*kk+1]};
            mma16816(l2, a, ones2);
        }

        // ---- O += P * V ----
        {
            int vkey = (lane & 15);
            int dhalf = ((lane >> 4) & 1) * 16;
            #pragma unroll
            for (int kk = 0; kk < 4; kk++) {
                uint32_t a[4] = {h0[2*kk], h1[2*kk], h0[2*kk+1], h1[2*kk+1]};
                #pragma unroll
                for (int jp = 0; jp < 4; jp++) {
                    uint32_t off = SW128((uint32_t)((16 * kk + vkey) * 128 + jp * 32 + dhalf));
                    uint32_t bh[4];
                    ldsm_x4t(bh, vh_b + off);
                    mma16816(O[2*jp],   a, bh);
                    mma16816(O[2*jp+1], a, bh + 2);
                }
            }
        }
    }

    // ---- epilogue: l already fully reduced by MMA ----
    float inv0 = 1.f / l2[0];
    float inv1 = 1.f / l2[2];

    const int col = 2 * (lane & 3);
    if (qpos0 < L) {
        float* o0 = out + ((size_t)(start + qpos0) * HEADS + h) * DH;
        #pragma unroll
        for (int jd = 0; jd < 8; jd++)
            *reinterpret_cast<float2*>(o0 + 8 * jd + col) =
                make_float2(O[jd][0] * inv0, O[jd][1] * inv0);
    }
    if (qpos1 < L) {
        float* o1 = out + ((size_t)(start + qpos1) * HEADS + h) * DH;
        #pragma unroll
        for (int jd = 0; jd < 8; jd++)
            *reinterpret_cast<float2*>(o1 + 8 * jd + col) =
                make_float2(O[jd][2] * inv1, O[jd][3] * inv1);
    }
}

extern "C" void kernel_launch(void* const* d_in, const int* in_sizes, int n_in,
                              void* d_out, int out_size)
{
    const float* q  = (const float*)d_in[0];
    const float* kv = (const float*)d_in[1];
    const int*   cu = (const int*)d_in[2];
    const int total   = in_sizes[0] / (HEADS * DH);
    const int nseq    = in_sizes[2] - 1;
    const int mblocks = (total + BM - 1) / BM;

    const int nitems = total * HKV * 32;
    convert_kv_kernel<<<(nitems + 255) / 256, 256>>>(kv, nitems);

    static int smem_set = 0;
    if (!smem_set) {
        cudaFuncSetAttribute(varlen_attn_hmma5,
                             cudaFuncAttributeMaxDynamicSharedMemorySize, SMEM_DYN);
        smem_set = 1;
    }
    dim3 grid(mblocks, nseq, HEADS);
    varlen_attn_hmma5<<<grid, NTH, SMEM_DYN>>>(q, cu, (float*)d_out);
}

// round 8
// speedup vs baseline: 11.7931x; 1.0398x over previous
#include <cuda_runtime.h>
#include <cuda_fp16.h>
#include <cstdint>

#define HEADS 16
#define HKV   4
#define DH    64
#define BM    128
#define BN    64
#define NTH   256
#define TMAX  8192

#define SW128(x) ((x) ^ (((x) >> 3) & 0x70))

// fp16 KV planes: 0=K, 1=V  [hkv][token][dim]
__device__ __align__(16) __half g_kvh[2][HKV][TMAX][DH];

__device__ __forceinline__ uint32_t smem_u32(const void* p) {
    uint32_t a;
    asm("{ .reg .u64 t; cvta.to.shared.u64 t, %1; cvt.u32.u64 %0, t; }"
        : "=r"(a) : "l"(p));
    return a;
}

__device__ __forceinline__ float ex2(float x) {
    float y; asm("ex2.approx.f32 %0, %1;" : "=f"(y) : "f"(x)); return y;
}
__device__ __forceinline__ uint32_t ex2h2(uint32_t x) {
    uint32_t r; asm("ex2.approx.f16x2 %0, %1;" : "=r"(r) : "r"(x)); return r;
}
__device__ __forceinline__ uint32_t hmax2u(uint32_t a, uint32_t b) {
    uint32_t r; asm("max.f16x2 %0, %1, %2;" : "=r"(r) : "r"(a), "r"(b)); return r;
}
__device__ __forceinline__ uint32_t hsub2u(uint32_t a, uint32_t b) {
    uint32_t r; asm("sub.f16x2 %0, %1, %2;" : "=r"(r) : "r"(a), "r"(b)); return r;
}

__device__ __forceinline__ void ldsm_x4(uint32_t* r, uint32_t addr) {
    asm volatile("ldmatrix.sync.aligned.m8n8.x4.shared.b16 {%0,%1,%2,%3}, [%4];"
        : "=r"(r[0]), "=r"(r[1]), "=r"(r[2]), "=r"(r[3]) : "r"(addr));
}
__device__ __forceinline__ void ldsm_x4t(uint32_t* r, uint32_t addr) {
    asm volatile("ldmatrix.sync.aligned.m8n8.x4.trans.shared.b16 {%0,%1,%2,%3}, [%4];"
        : "=r"(r[0]), "=r"(r[1]), "=r"(r[2]), "=r"(r[3]) : "r"(addr));
}

__device__ __forceinline__ void mma16816(float* d, const uint32_t* a, const uint32_t* b) {
    asm volatile("mma.sync.aligned.m16n8k16.row.col.f32.f16.f16.f32 "
        "{%0,%1,%2,%3}, {%4,%5,%6,%7}, {%8,%9}, {%0,%1,%2,%3};"
        : "+f"(d[0]), "+f"(d[1]), "+f"(d[2]), "+f"(d[3])
        : "r"(a[0]), "r"(a[1]), "r"(a[2]), "r"(a[3]), "r"(b[0]), "r"(b[1]));
}

__device__ __forceinline__ uint32_t packh(float x0, float x1) {
    uint32_t r; asm("cvt.rn.f16x2.f32 %0, %1, %2;" : "=r"(r) : "f"(x1), "f"(x0));
    return r;
}

// ---------------- pre-pass: fp32 KV -> fp16 planes ----------------
__global__ void convert_kv_kernel(const float* __restrict__ kv, int nitems) {
    int idx = blockIdx.x * blockDim.x + threadIdx.x;
    if (idx >= nitems) return;               // nitems = total*HKV*32
    int c2  = idx & 31;
    int hk  = (idx >> 5) & 3;
    int tok = idx >> 7;
    const float* base = kv + (size_t)tok * (2 * HKV * DH) + hk * DH + 2 * c2;
    float2 kk = *reinterpret_cast<const float2*>(base);
    float2 vv = *reinterpret_cast<const float2*>(base + HKV * DH);
    *reinterpret_cast<uint32_t*>(&g_kvh[0][hk][tok][2 * c2]) = packh(kk.x, kk.y);
    *reinterpret_cast<uint32_t*>(&g_kvh[1][hk][tok][2 * c2]) = packh(vv.x, vv.y);
}

// cp.async one KV tile (K + V planes) into 16KB smem stage with SW128 swizzle
__device__ __forceinline__ void prefetch_tile(uint32_t smb, int buf, int tid,
                                              int hkv, int tok0, int L, int k0) {
    uint32_t dstb = smb + (uint32_t)buf * 16384u;
    #pragma unroll
    for (int p = 0; p < 2; p++) {
        const __half* plane = &g_kvh[p][hkv][0][0];
        #pragma unroll
        for (int i = 0; i < 2; i++) {
            int u   = i * NTH + tid;            // 512 granules of 16B per plane
            int key = u >> 3, g = u & 7;
            uint32_t dst = dstb + (uint32_t)p * 8192u
                         + SW128((uint32_t)(key * 128 + g * 16));
            const void* src = plane + (size_t)(tok0 + key) * DH + g * 8;
            unsigned n = (k0 + key < L) ? 16u : 0u;   // zfill OOB keys
            asm volatile("cp.async.cg.shared.global [%0], [%1], 16, %2;"
                         :: "r"(dst), "l"(src), "r"(n));
        }
    }
}

#define SMEM_DYN 65536   // 3x16KB KV stages + 16KB Q staging

__global__ __launch_bounds__(NTH, 2) void varlen_attn_hmma6(
    const float* __restrict__ q,
    const int*   __restrict__ cu,
    float*       __restrict__ out)
{
    const int seq   = blockIdx.y;
    const int h     = blockIdx.z;
    const int start = cu[seq];
    const int L     = cu[seq + 1] - start;
    const int m0    = (gridDim.x - 1 - blockIdx.x) * BM;   // longest CTAs first
    if (m0 >= L) return;

    extern __shared__ uint8_t sm[];
    const uint32_t smb = smem_u32(sm);

    const int tid  = threadIdx.x;
    const int wid  = tid >> 5;
    const int lane = tid & 31;
    const int hkv  = h >> 2;
    const float SCALE = 0.125f * 1.4426950408889634f;

    const int klim_cta = (L < m0 + BM) ? L : (m0 + BM);
    const int ntiles   = (klim_cta + BN - 1) / BN;

    // prologue: stages for tiles 0 and 1
    prefetch_tile(smb, 0, tid, hkv, start, L, 0);
    asm volatile("cp.async.commit_group;" ::: "memory");

    // ---- stage Q (scaled, fp16) ----
    #pragma unroll
    for (int it = 0; it < 16; it++) {
        int u = it * NTH + tid;
        int row = u >> 5, c2 = u & 31;
        float2 qv = make_float2(0.f, 0.f);
        if (m0 + row < L)
            qv = *reinterpret_cast<const float2*>(
                q + ((size_t)(start + m0 + row) * HEADS + h) * DH + 2 * c2);
        uint32_t sw = SW128((uint32_t)(row * 128 + c2 * 4));
        *reinterpret_cast<uint32_t*>(sm + 49152 + sw) = packh(qv.x * SCALE, qv.y * SCALE);
    }

    if (1 < ntiles)
        prefetch_tile(smb, 1, tid, hkv, start + BN, L, BN);
    asm volatile("cp.async.commit_group;" ::: "memory");
    __syncthreads();

    uint32_t qh[4][4];
    {
        int qrow = wid * 16 + (lane & 15);
        #pragma unroll
        for (int kk = 0; kk < 4; kk++) {
            uint32_t off = SW128((uint32_t)(qrow * 128 + kk * 32 + ((lane >> 4) & 1) * 16));
            ldsm_x4(qh[kk], smb + 49152 + off);
        }
    }

    // ---- per-thread state ----
    float O[8][4];
    #pragma unroll
    for (int j = 0; j < 8; j++)
        #pragma unroll
        for (int e = 0; e < 4; e++) O[j][e] = 0.f;
    float l2[4] = {0.f, 0.f, 0.f, 0.f};      // MMA accumulator: l0 in [0], l1 in [2]
    float mrow0 = -1e30f, mrow1 = -1e30f;

    const int qpos0 = m0 + wid * 16 + (lane >> 2);
    const int qpos1 = qpos0 + 8;
    const int klim0 = (qpos0 + 1 < L) ? qpos0 + 1 : L;
    const int klim1 = (qpos1 + 1 < L) ? qpos1 + 1 : L;
    const int qmax_warp = m0 + wid * 16 + 15;
    const int qmin_warp = m0 + wid * 16;

    const uint32_t ones2[2] = {0x3C003C00u, 0x3C003C00u};   // fp16 1.0 pair

    int buf = 0;
    for (int t = 0; t < ntiles; t++, buf = (buf == 2) ? 0 : buf + 1) {
        const int k0 = t * BN;
        asm volatile("cp.async.wait_group 1;" ::: "memory");   // tile t landed
        __syncthreads();                                       // buf (t+2)%3 free
        if (t + 2 < ntiles)
            prefetch_tile(smb, (buf == 0) ? 2 : buf - 1, tid, hkv,
                          start + k0 + 2 * BN, L, k0 + 2 * BN);
        asm volatile("cp.async.commit_group;" ::: "memory");

        if (k0 > qmax_warp) continue;   // fully-masked tile for this warp

        const uint32_t kh_b = smb + (uint32_t)(buf * 16384);
        const uint32_t vh_b = kh_b + 8192;

        // ---- S = Q * K^T  (kk outer: 8 independent accumulators per batch) ----
        float S[8][4];
        #pragma unroll
        for (int j = 0; j < 8; j++)
            #pragma unroll
            for (int e = 0; e < 4; e++) S[j][e] = 0.f;
        {
            int key = ((lane >> 4) & 1) * 8 + (lane & 7);
            int dhalf = ((lane >> 3) & 1) * 16;
            #pragma unroll
            for (int kk = 0; kk < 4; kk++) {
                uint32_t bh[4][4];
                #pragma unroll
                for (int jp = 0; jp < 4; jp++)
                    ldsm_x4(bh[jp], kh_b +
                        SW128((uint32_t)((16 * jp + key) * 128 + kk * 32 + dhalf)));
                #pragma unroll
                for (int jp = 0; jp < 4; jp++) {
                    mma16816(S[2*jp],   qh[kk], bh[jp]);
                    mma16816(S[2*jp+1], qh[kk], bh[jp] + 2);
                }
            }
        }

        // ---- pack scores to f16x2 rows (mask in fp32 on edge tiles) ----
        uint32_t h0[8], h1[8];   // h0 = row-group0 pairs, h1 = row-group1
        const bool full = (k0 + BN <= L) && (k0 + BN <= qmin_warp + 1);
        if (full) {
            #pragma unroll
            for (int j = 0; j < 8; j++) {
                h0[j] = packh(S[j][0], S[j][1]);
                h1[j] = packh(S[j][2], S[j][3]);
            }
        } else {
            const int jm0 = klim0 - k0, jm1 = klim1 - k0;
            #pragma unroll
            for (int j = 0; j < 8; j++) {
                int kg = 8 * j + 2 * (lane & 3);
                float a0 = (kg     < jm0) ? S[j][0] : -1e30f;  // -> -inf in fp16
                float a1 = (kg + 1 < jm0) ? S[j][1] : -1e30f;
                float a2 = (kg     < jm1) ? S[j][2] : -1e30f;
                float a3 = (kg + 1 < jm1) ? S[j][3] : -1e30f;
                h0[j] = packh(a0, a1);
                h1[j] = packh(a2, a3);
            }
        }

        // ---- tile max (f16x2 tree + packed quad shuffles) ----
        uint32_t t0 = hmax2u(hmax2u(hmax2u(h0[0], h0[1]), hmax2u(h0[2], h0[3])),
                             hmax2u(hmax2u(h0[4], h0[5]), hmax2u(h0[6], h0[7])));
        uint32_t t1 = hmax2u(hmax2u(hmax2u(h1[0], h1[1]), hmax2u(h1[2], h1[3])),
                             hmax2u(hmax2u(h1[4], h1[5]), hmax2u(h1[6], h1[7])));
        uint32_t tm;
        {
            __half2 a = *reinterpret_cast<__half2*>(&t0);
            __half2 b = *reinterpret_cast<__half2*>(&t1);
            __half2 c = __halves2half2(__hmax(__low2half(a), __high2half(a)),
                                       __hmax(__low2half(b), __high2half(b)));
            tm = *reinterpret_cast<uint32_t*>(&c);
        }
        tm = hmax2u(tm, __shfl_xor_sync(0xffffffffu, tm, 1));
        tm = hmax2u(tm, __shfl_xor_sync(0xffffffffu, tm, 2));
        __half2 tmh = *reinterpret_cast<__half2*>(&tm);

        // mnew rounded to fp16 so p / corr / l / O all share one constant
        float mnew0 = fmaxf(mrow0, __low2float(tmh));
        float mnew1 = fmaxf(mrow1, __high2float(tmh));
        __half mn0 = __float2half_rn(mnew0);
        __half mn1 = __float2half_rn(mnew1);
        mnew0 = __half2float(mn0);
        mnew1 = __half2float(mn1);

        // warp-uniform skip: if no lane's max changed, corr == 1 exactly
        bool changed = (mnew0 != mrow0) || (mnew1 != mrow1);
        if (__any_sync(0xffffffffu, changed)) {
            float corr0 = ex2(mrow0 - mnew0);   // 0 on first tile
            float corr1 = ex2(mrow1 - mnew1);
            mrow0 = mnew0; mrow1 = mnew1;
            l2[0] *= corr0; l2[2] *= corr1;
            #pragma unroll
            for (int j = 0; j < 8; j++) {
                O[j][0] *= corr0; O[j][1] *= corr0;
                O[j][2] *= corr1; O[j][3] *= corr1;
            }
        }

        // ---- P = exp2(S - m) in f16x2 (already packed for MMA) ----
        uint32_t m00, m11;
        {
            __half2 x = __half2half2(mn0);
            __half2 y = __half2half2(mn1);
            m00 = *reinterpret_cast<uint32_t*>(&x);
            m11 = *reinterpret_cast<uint32_t*>(&y);
        }
        #pragma unroll
        for (int j = 0; j < 8; j++) {
            h0[j] = ex2h2(hsub2u(h0[j], m00));
            h1[j] = ex2h2(hsub2u(h1[j], m11));
        }

        // ---- l += P * ones (tensor pipe, exact fp32 row-sums) ----
        #pragma unroll
        for (int kk = 0; kk < 4; kk++) {
            uint32_t a[4] = {h0[2*kk], h1[2*kk], h0[2*kk+1], h1[2*kk+1]};
            mma16816(l2, a, ones2);
        }

        // ---- O += P * V ----
        {
            int vkey = (lane & 15);
            int dhalf = ((lane >> 4) & 1) * 16;
            #pragma unroll
            for (int kk = 0; kk < 4; kk++) {
                uint32_t a[4] = {h0[2*kk], h1[2*kk], h0[2*kk+1], h1[2*kk+1]};
                uint32_t bh[4][4];
                #pragma unroll
                for (int jp = 0; jp < 4; jp++)
                    ldsm_x4t(bh[jp], vh_b +
                        SW128((uint32_t)((16 * kk + vkey) * 128 + jp * 32 + dhalf)));
                #pragma unroll
                for (int jp = 0; jp < 4; jp++) {
                    mma16816(O[2*jp],   a, bh[jp]);
                    mma16816(O[2*jp+1], a, bh[jp] + 2);
                }
            }
        }
    }

    // ---- epilogue: l already fully reduced by MMA ----
    float inv0 = 1.f / l2[0];
    float inv1 = 1.f / l2[2];

    const int col = 2 * (lane & 3);
    if (qpos0 < L) {
        float* o0 = out + ((size_t)(start + qpos0) * HEADS + h) * DH;
        #pragma unroll
        for (int jd = 0; jd < 8; jd++)
            *reinterpret_cast<float2*>(o0 + 8 * jd + col) =
                make_float2(O[jd][0] * inv0, O[jd][1] * inv0);
    }
    if (qpos1 < L) {
        float* o1 = out + ((size_t)(start + qpos1) * HEADS + h) * DH;
        #pragma unroll
        for (int jd = 0; jd < 8; jd++)
            *reinterpret_cast<float2*>(o1 + 8 * jd + col) =
                make_float2(O[jd][2] * inv1, O[jd][3] * inv1);
    }
}

extern "C" void kernel_launch(void* const* d_in, const int* in_sizes, int n_in,
                              void* d_out, int out_size)
{
    const float* q  = (const float*)d_in[0];
    const float* kv = (const float*)d_in[1];
    const int*   cu = (const int*)d_in[2];
    const int total   = in_sizes[0] / (HEADS * DH);
    const int nseq    = in_sizes[2] - 1;
    const int mblocks = (total + BM - 1) / BM;

    const int nitems = total * HKV * 32;
    convert_kv_kernel<<<(nitems + 255) / 256, 256>>>(kv, nitems);

    static int smem_set = 0;
    if (!smem_set) {
        cudaFuncSetAttribute(varlen_attn_hmma6,
                             cudaFuncAttributeMaxDynamicSharedMemorySize, SMEM_DYN);
        smem_set = 1;
    }
    dim3 grid(mblocks, nseq, HEADS);
    varlen_attn_hmma6<<<grid, NTH, SMEM_DYN>>>(q, cu, (float*)d_out);
}